// round 12
// baseline (speedup 1.0000x reference)
#include <cuda_runtime.h>
#include <cuda_bf16.h>
#include <cuda_fp16.h>
#include <math.h>
#include <stdint.h>

// Problem constants
#define Bn  2
#define Tn  2048
#define Cn  1024
#define Hn  16
#define HDn 64
#define QKV_N (3*Cn)          // 3072
#define Mrows (Bn*Tn)         // 4096

// Scratch (allocation-free: __device__ globals)
__device__ float g_qkv[(size_t)Mrows * QKV_N];
__device__ __half g_xhi[(size_t)Mrows * Cn];
__device__ __half g_xlo[(size_t)Mrows * Cn];
__device__ __half g_wah[(size_t)Cn * QKV_N];     // fp16(w_attn), unsplit
__device__ __half g_wph[(size_t)Cn * Cn];        // fp16(w_proj), unsplit
__device__ __half g_yhi[(size_t)Mrows * Cn];
__device__ __half g_ylo[(size_t)Mrows * Cn];

// ===========================================================================
// fp32 -> fp16 hi/lo split  and  fp32 -> fp16 convert (weights)
// ===========================================================================
__global__ __launch_bounds__(256)
void split2h(const float* __restrict__ src, __half* __restrict__ hi,
             __half* __restrict__ lo, int n4)
{
    int i = blockIdx.x * blockDim.x + threadIdx.x;
    if (i >= n4) return;
    float4 v = ((const float4*)src)[i];
    __half hx = __float2half_rn(v.x), hy = __float2half_rn(v.y);
    __half hz = __float2half_rn(v.z), hw = __float2half_rn(v.w);
    ((__half2*)hi)[2 * i]     = __half2(hx, hy);
    ((__half2*)hi)[2 * i + 1] = __half2(hz, hw);
    ((__half2*)lo)[2 * i] = __half2(
        __float2half_rn(v.x - __half2float(hx)),
        __float2half_rn(v.y - __half2float(hy)));
    ((__half2*)lo)[2 * i + 1] = __half2(
        __float2half_rn(v.z - __half2float(hz)),
        __float2half_rn(v.w - __half2float(hw)));
}

__global__ __launch_bounds__(256)
void conv_h(const float* __restrict__ src, __half* __restrict__ dst, int n4)
{
    int i = blockIdx.x * blockDim.x + threadIdx.x;
    if (i >= n4) return;
    float4 v = ((const float4*)src)[i];
    ((__half2*)dst)[2 * i]     = __floats2half2_rn(v.x, v.y);
    ((__half2*)dst)[2 * i + 1] = __floats2half2_rn(v.z, v.w);
}

// ===========================================================================
// Pipelined fp16 2-pass GEMM (R10 winner, unchanged): C = (Ahi+Alo)@Bh + bias
// ===========================================================================
#define GBM 128
#define GBN 128
#define GBK 32
#define ASTR 40
#define BSTR 136
#define OFF_AHI 0
#define OFF_ALO 10240
#define OFF_BHI 20480
#define STAGE_BYTES 29184
#define GEMM_SMEM (2*STAGE_BYTES)

__device__ __forceinline__ void cpasync16(uint32_t dst, const void* src) {
    asm volatile("cp.async.cg.shared.global [%0], [%1], 16;" :: "r"(dst), "l"(src));
}
__device__ __forceinline__ void ldsm4(uint32_t r[4], uint32_t addr) {
    asm volatile("ldmatrix.sync.aligned.m8n8.x4.shared.b16 {%0,%1,%2,%3}, [%4];"
                 : "=r"(r[0]), "=r"(r[1]), "=r"(r[2]), "=r"(r[3]) : "r"(addr));
}
__device__ __forceinline__ void ldsm4t(uint32_t r[4], uint32_t addr) {
    asm volatile("ldmatrix.sync.aligned.m8n8.x4.trans.shared.b16 {%0,%1,%2,%3}, [%4];"
                 : "=r"(r[0]), "=r"(r[1]), "=r"(r[2]), "=r"(r[3]) : "r"(addr));
}
__device__ __forceinline__ void mma_f16(float d[4], const uint32_t a[4],
                                        uint32_t b0, uint32_t b1) {
    asm volatile(
        "mma.sync.aligned.m16n8k16.row.col.f32.f16.f16.f32 "
        "{%0,%1,%2,%3}, {%4,%5,%6,%7}, {%8,%9}, {%0,%1,%2,%3};"
        : "+f"(d[0]), "+f"(d[1]), "+f"(d[2]), "+f"(d[3])
        : "r"(a[0]), "r"(a[1]), "r"(a[2]), "r"(a[3]), "r"(b0), "r"(b1));
}

__global__ __launch_bounds__(256, 2)
void hgemm_2p(const __half* __restrict__ Ahi_g, const __half* __restrict__ Alo_g,
              const __half* __restrict__ Bh_g,
              const float* __restrict__ bias, float* __restrict__ C,
              int M, int N, int K)
{
    extern __shared__ char gsm[];
    const int tid  = threadIdx.x;
    const int warp = tid >> 5;
    const int lane = tid & 31;
    const int g  = lane >> 2;
    const int tg = lane & 3;

    const int bm = blockIdx.y * GBM;
    const int bn = blockIdx.x * GBN;
    const int warp_m = (warp >> 1) * 32;
    const int warp_n = (warp & 1) * 64;

    const int ar = tid >> 2, ac = (tid & 3) * 8;
    const int br = tid >> 4, bc = (tid & 15) * 8;
    const __half* aih = Ahi_g + (size_t)(bm + ar) * K + ac;
    const __half* ail = Alo_g + (size_t)(bm + ar) * K + ac;
    const __half* bhg = Bh_g  + (size_t)br * N + bn + bc;
    const size_t a64 = (size_t)64 * K;
    const size_t b16 = (size_t)16 * N;

    const uint32_t smb = (uint32_t)__cvta_generic_to_shared(gsm);
    const uint32_t dA  = (uint32_t)(ar * ASTR + ac) * 2;
    const uint32_t dA2 = (uint32_t)((ar + 64) * ASTR + ac) * 2;
    const uint32_t dB  = (uint32_t)(br * BSTR + bc) * 2;
    const uint32_t dB2 = (uint32_t)((br + 16) * BSTR + bc) * 2;

    float acc[2][8][4];
    #pragma unroll
    for (int mt = 0; mt < 2; mt++)
        #pragma unroll
        for (int nt = 0; nt < 8; nt++)
            #pragma unroll
            for (int i = 0; i < 4; i++) acc[mt][nt][i] = 0.f;

    const int NK = K / GBK;

    #define ISSUE_STAGE(s, kit) do {                                         \
        uint32_t so = smb + (uint32_t)(s) * STAGE_BYTES;                     \
        size_t ka = (size_t)(kit) * GBK;                                     \
        size_t kb = (size_t)(kit) * GBK * (size_t)N;                         \
        cpasync16(so + OFF_AHI + dA,  aih + ka);                             \
        cpasync16(so + OFF_AHI + dA2, aih + a64 + ka);                       \
        cpasync16(so + OFF_ALO + dA,  ail + ka);                             \
        cpasync16(so + OFF_ALO + dA2, ail + a64 + ka);                       \
        cpasync16(so + OFF_BHI + dB,  bhg + kb);                             \
        cpasync16(so + OFF_BHI + dB2, bhg + b16 + kb);                       \
        asm volatile("cp.async.commit_group;");                              \
    } while (0)

    ISSUE_STAGE(0, 0);

    const int a_r = lane & 15;
    const int a_c = (lane >> 4) * 8;

    for (int it = 0; it < NK; it++) {
        if (it + 1 < NK) {
            ISSUE_STAGE((it + 1) & 1, it + 1);
            asm volatile("cp.async.wait_group 1;");
        } else {
            asm volatile("cp.async.wait_group 0;");
        }
        __syncthreads();

        const uint32_t sb = smb + (uint32_t)(it & 1) * STAGE_BYTES;
        #pragma unroll
        for (int ks = 0; ks < 2; ks++) {
            const int kk = ks * 16;
            uint32_t ah[2][4], al[2][4];
            #pragma unroll
            for (int mt = 0; mt < 2; mt++) {
                uint32_t off = (uint32_t)((warp_m + mt * 16 + a_r) * ASTR + kk + a_c) * 2;
                ldsm4(ah[mt], sb + OFF_AHI + off);
                ldsm4(al[mt], sb + OFF_ALO + off);
            }
            #pragma unroll
            for (int np = 0; np < 4; np++) {
                uint32_t bh[4];
                uint32_t off = (uint32_t)((kk + a_r) * BSTR + warp_n + np * 16 + a_c) * 2;
                ldsm4t(bh, sb + OFF_BHI + off);
                #pragma unroll
                for (int pass = 0; pass < 2; pass++) {
                    #pragma unroll
                    for (int half = 0; half < 2; half++) {
                        const int nt = np * 2 + half;
                        #pragma unroll
                        for (int mt = 0; mt < 2; mt++) {
                            mma_f16(acc[mt][nt], pass ? al[mt] : ah[mt],
                                    bh[half * 2], bh[half * 2 + 1]);
                        }
                    }
                }
            }
        }
        __syncthreads();
    }

    #pragma unroll
    for (int nt = 0; nt < 8; nt++) {
        const int col = bn + warp_n + nt * 8 + 2 * tg;
        const float2 bs = *(const float2*)&bias[col];
        #pragma unroll
        for (int mt = 0; mt < 2; mt++) {
            const int row0 = bm + warp_m + mt * 16 + g;
            float2 o0 = make_float2(acc[mt][nt][0] + bs.x, acc[mt][nt][1] + bs.y);
            float2 o1 = make_float2(acc[mt][nt][2] + bs.x, acc[mt][nt][3] + bs.y);
            *(float2*)&C[(size_t)row0 * N + col]       = o0;
            *(float2*)&C[(size_t)(row0 + 8) * N + col] = o1;
        }
    }
    #undef ISSUE_STAGE
}

// ===========================================================================
// Flash attention v4: QK fp16 (m16n8k16), PV fp16 2-pass (P hi/lo, V plain).
// 256 threads (8 warps), BQ=128, KV tiles 64. Output y as fp16 hi/lo.
// ===========================================================================
#define AT_BQ   128
#define AT_BKV  64
#define KPAD    68          // Q fp32 staging stride (words)
#define KHW     36          // K fp16 row stride in 32-bit words (72 halves)
#define VSTR    72          // V pair-row stride (uint32 words)
#define SCALE   0.125f

__global__ __launch_bounds__(256)
void attn_tc(const float* __restrict__ qkv,
             __half* __restrict__ yhi, __half* __restrict__ ylo)
{
    __shared__ float pool[AT_BQ * KPAD];            // 8704 words (Q staging)
    uint32_t* Kw = (uint32_t*)pool;                 // K fp16: 64*36 = 2304 words
    uint32_t* Vp = (uint32_t*)pool + AT_BKV * KHW;  // V fp16 pairs: 32*72 = 2304

    const int b = blockIdx.z, h = blockIdx.y;
    const int qtile = gridDim.x - 1 - blockIdx.x;   // heavy tiles first
    const int q0 = qtile * AT_BQ;
    const int tid  = threadIdx.x;
    const int warp = tid >> 5;
    const int lane = tid & 31;
    const int g  = lane >> 2;
    const int tg = lane & 3;

    // ---- stage Q tile (pre-scaled fp32), then build fp16 A-frags ----
    {
        const float* qg = qkv + ((size_t)(b * Tn + q0)) * QKV_N + h * HDn;
        #pragma unroll
        for (int itr = 0; itr < 8; itr++) {
            int f = itr * 256 + tid;
            int r = f >> 4, c = (f & 15) << 2;
            float4 v = *(const float4*)(qg + (size_t)r * QKV_N + c);
            v.x *= SCALE; v.y *= SCALE; v.z *= SCALE; v.w *= SCALE;
            *(float4*)&pool[r * KPAD + c] = v;
        }
    }
    __syncthreads();

    uint32_t Aq[4][4];   // 4 k16-steps
    {
        const int r0 = warp * 16 + g;
        #pragma unroll
        for (int kk = 0; kk < 4; kk++) {
            const int c0 = kk * 16 + 2 * tg;
            __half2 t;
            t = __floats2half2_rn(pool[r0 * KPAD + c0],      pool[r0 * KPAD + c0 + 1]);
            Aq[kk][0] = *(uint32_t*)&t;
            t = __floats2half2_rn(pool[(r0+8) * KPAD + c0],  pool[(r0+8) * KPAD + c0 + 1]);
            Aq[kk][1] = *(uint32_t*)&t;
            t = __floats2half2_rn(pool[r0 * KPAD + c0 + 8],  pool[r0 * KPAD + c0 + 9]);
            Aq[kk][2] = *(uint32_t*)&t;
            t = __floats2half2_rn(pool[(r0+8) * KPAD + c0+8],pool[(r0+8) * KPAD + c0+9]);
            Aq[kk][3] = *(uint32_t*)&t;
        }
    }
    __syncthreads();

    float O[8][4];
    #pragma unroll
    for (int nt = 0; nt < 8; nt++)
        #pragma unroll
        for (int i = 0; i < 4; i++) O[nt][i] = 0.f;

    float m0 = -INFINITY, m1 = -INFINITY;
    float l0 = 0.f, l1 = 0.f;

    const int qi0 = q0 + warp * 16 + g;
    const int qi1 = qi0 + 8;
    const int w_qmax = q0 + warp * 16 + 15;
    const int w_qmin = q0 + warp * 16;

    for (int kt = 0; kt < q0 + AT_BQ; kt += AT_BKV) {
        // ---- stage K as fp16 (row-major, 72-half stride) ----
        {
            const float* kg = qkv + ((size_t)(b * Tn + kt)) * QKV_N + Cn + h * HDn;
            #pragma unroll
            for (int itr = 0; itr < 4; itr++) {
                int f = itr * 256 + tid;
                int r = f >> 4, c = (f & 15) << 2;
                float4 kv4 = *(const float4*)(kg + (size_t)r * QKV_N + c);
                __half2 w0 = __floats2half2_rn(kv4.x, kv4.y);
                __half2 w1 = __floats2half2_rn(kv4.z, kv4.w);
                uint2 st = make_uint2(*(uint32_t*)&w0, *(uint32_t*)&w1);
                *(uint2*)&Kw[r * KHW + (f & 15) * 2] = st;
            }
        }
        // ---- stage V as fp16 row-pair-packed ----
        {
            const float* vg = qkv + ((size_t)(b * Tn + kt)) * QKV_N + 2 * Cn + h * HDn;
            #pragma unroll
            for (int itr = 0; itr < 2; itr++) {
                int f = itr * 256 + tid;
                int p  = f >> 4;
                int c4 = (f & 15) * 4;
                const float* r0p = vg + (size_t)(2 * p) * QKV_N + c4;
                float4 v0 = *(const float4*)r0p;
                float4 v1 = *(const float4*)(r0p + QKV_N);
                __half2 h0 = __floats2half2_rn(v0.x, v1.x);
                __half2 h1 = __floats2half2_rn(v0.y, v1.y);
                __half2 h2 = __floats2half2_rn(v0.z, v1.z);
                __half2 h3 = __floats2half2_rn(v0.w, v1.w);
                *(uint4*)&Vp[p * VSTR + c4] = make_uint4(
                    *(uint32_t*)&h0, *(uint32_t*)&h1,
                    *(uint32_t*)&h2, *(uint32_t*)&h3);
            }
        }
        __syncthreads();

        if (kt <= w_qmax) {
            // ---- S = Q @ K^T (fp16 m16n8k16, 32 MMAs) ----
            float S[8][4];
            #pragma unroll
            for (int nt = 0; nt < 8; nt++) {
                S[nt][0] = S[nt][1] = S[nt][2] = S[nt][3] = 0.f;
            }
            #pragma unroll
            for (int kk = 0; kk < 4; kk++) {
                #pragma unroll
                for (int nt = 0; nt < 8; nt++) {
                    const int rw = (nt * 8 + g) * KHW + kk * 8 + tg;
                    mma_f16(S[nt], Aq[kk], Kw[rw], Kw[rw + 4]);
                }
            }

            const bool need_mask = (kt + AT_BKV - 1 > w_qmin);
            if (need_mask) {
                #pragma unroll
                for (int nt = 0; nt < 8; nt++) {
                    int j0 = kt + nt * 8 + 2 * tg;
                    int j1 = j0 + 1;
                    if (j0 > qi0) S[nt][0] = -INFINITY;
                    if (j1 > qi0) S[nt][1] = -INFINITY;
                    if (j0 > qi1) S[nt][2] = -INFINITY;
                    if (j1 > qi1) S[nt][3] = -INFINITY;
                }
            }

            // ---- online softmax ----
            float mc0 = -INFINITY, mc1 = -INFINITY;
            #pragma unroll
            for (int nt = 0; nt < 8; nt++) {
                mc0 = fmaxf(mc0, fmaxf(S[nt][0], S[nt][1]));
                mc1 = fmaxf(mc1, fmaxf(S[nt][2], S[nt][3]));
            }
            mc0 = fmaxf(mc0, __shfl_xor_sync(0xffffffffu, mc0, 1));
            mc0 = fmaxf(mc0, __shfl_xor_sync(0xffffffffu, mc0, 2));
            mc1 = fmaxf(mc1, __shfl_xor_sync(0xffffffffu, mc1, 1));
            mc1 = fmaxf(mc1, __shfl_xor_sync(0xffffffffu, mc1, 2));

            float mn0 = fmaxf(m0, mc0);
            float mn1 = fmaxf(m1, mc1);
            float corr0 = __expf(m0 - mn0);
            float corr1 = __expf(m1 - mn1);
            m0 = mn0; m1 = mn1;

            float ps0 = 0.f, ps1 = 0.f;
            #pragma unroll
            for (int nt = 0; nt < 8; nt++) {
                S[nt][0] = __expf(S[nt][0] - mn0);
                S[nt][1] = __expf(S[nt][1] - mn0);
                S[nt][2] = __expf(S[nt][2] - mn1);
                S[nt][3] = __expf(S[nt][3] - mn1);
                ps0 += S[nt][0] + S[nt][1];
                ps1 += S[nt][2] + S[nt][3];
            }
            ps0 += __shfl_xor_sync(0xffffffffu, ps0, 1);
            ps0 += __shfl_xor_sync(0xffffffffu, ps0, 2);
            ps1 += __shfl_xor_sync(0xffffffffu, ps1, 1);
            ps1 += __shfl_xor_sync(0xffffffffu, ps1, 2);
            l0 = l0 * corr0 + ps0;
            l1 = l1 * corr1 + ps1;

            #pragma unroll
            for (int nt = 0; nt < 8; nt++) {
                O[nt][0] *= corr0; O[nt][1] *= corr0;
                O[nt][2] *= corr1; O[nt][3] *= corr1;
            }

            // ---- O += P @ V, fp16 2-pass (P hi/lo exact, V fp16) ----
            #pragma unroll
            for (int s = 0; s < 4; s++) {
                uint32_t aph[4], apl[4];
                const float pv[8] = {
                    S[2*s  ][0], S[2*s  ][1], S[2*s  ][2], S[2*s  ][3],
                    S[2*s+1][0], S[2*s+1][1], S[2*s+1][2], S[2*s+1][3]
                };
                #pragma unroll
                for (int q = 0; q < 4; q++) {
                    __half2 hp = __floats2half2_rn(pv[2*q], pv[2*q+1]);
                    aph[q] = *(uint32_t*)&hp;
                    float2 hf = __half22float2(hp);
                    __half2 lp = __floats2half2_rn(pv[2*q] - hf.x, pv[2*q+1] - hf.y);
                    apl[q] = *(uint32_t*)&lp;
                }
                const int pr0 = (8 * s + tg) * VSTR;
                const int pr1 = (8 * s + tg + 4) * VSTR;
                #pragma unroll
                for (int dd = 0; dd < 8; dd++) {
                    const int dc = dd * 8 + g;
                    uint32_t b0 = Vp[pr0 + dc];
                    uint32_t b1 = Vp[pr1 + dc];
                    mma_f16(O[dd], aph, b0, b1);
                    mma_f16(O[dd], apl, b0, b1);
                }
            }
        }
        __syncthreads();
    }

    // ---- finalize: divide by l, split to fp16 hi/lo, store ----
    const float inv0 = 1.f / l0;
    const float inv1 = 1.f / l1;
    const size_t row0 = (size_t)(b * Tn + qi0) * Cn + h * HDn;
    const size_t row1 = (size_t)(b * Tn + qi1) * Cn + h * HDn;
    #pragma unroll
    for (int nt = 0; nt < 8; nt++) {
        int c = nt * 8 + 2 * tg;
        float v00 = O[nt][0] * inv0, v01 = O[nt][1] * inv0;
        float v10 = O[nt][2] * inv1, v11 = O[nt][3] * inv1;
        __half h00 = __float2half_rn(v00), h01 = __float2half_rn(v01);
        __half h10 = __float2half_rn(v10), h11 = __float2half_rn(v11);
        *(__half2*)&yhi[row0 + c] = __half2(h00, h01);
        *(__half2*)&yhi[row1 + c] = __half2(h10, h11);
        *(__half2*)&ylo[row0 + c] = __half2(
            __float2half_rn(v00 - __half2float(h00)),
            __float2half_rn(v01 - __half2float(h01)));
        *(__half2*)&ylo[row1 + c] = __half2(
            __float2half_rn(v10 - __half2float(h10)),
            __float2half_rn(v11 - __half2float(h11)));
    }
}

// ---------------------------------------------------------------------------
// Launch
// ---------------------------------------------------------------------------
extern "C" void kernel_launch(void* const* d_in, const int* in_sizes, int n_in,
                              void* d_out, int out_size)
{
    const float* x      = (const float*)d_in[0];
    const float* w_attn = (const float*)d_in[1];
    const float* b_attn = (const float*)d_in[2];
    const float* w_proj = (const float*)d_in[3];
    const float* b_proj = (const float*)d_in[4];
    float* out = (float*)d_out;

    float* qkv_ptr; __half *xhi, *xlo, *wah, *wph, *yhi, *ylo;
    cudaGetSymbolAddress((void**)&qkv_ptr, g_qkv);
    cudaGetSymbolAddress((void**)&xhi, g_xhi);
    cudaGetSymbolAddress((void**)&xlo, g_xlo);
    cudaGetSymbolAddress((void**)&wah, g_wah);
    cudaGetSymbolAddress((void**)&wph, g_wph);
    cudaGetSymbolAddress((void**)&yhi, g_yhi);
    cudaGetSymbolAddress((void**)&ylo, g_ylo);

    cudaFuncSetAttribute(hgemm_2p, cudaFuncAttributeMaxDynamicSharedMemorySize, GEMM_SMEM);

    // 0) split x (hi/lo fp16); convert weights to fp16
    {
        int n4;
        n4 = (Mrows * Cn) / 4;
        split2h<<<(n4 + 255) / 256, 256>>>(x, xhi, xlo, n4);
        n4 = (Cn * QKV_N) / 4;
        conv_h<<<(n4 + 255) / 256, 256>>>(w_attn, wah, n4);
        n4 = (Cn * Cn) / 4;
        conv_h<<<(n4 + 255) / 256, 256>>>(w_proj, wph, n4);
    }
    // 1) QKV projection (fp16 2-pass)
    {
        dim3 grid(QKV_N / GBN, Mrows / GBM);
        hgemm_2p<<<grid, 256, GEMM_SMEM>>>(xhi, xlo, wah, b_attn,
                                           qkv_ptr, Mrows, QKV_N, Cn);
    }
    // 2) Causal attention (fp16 QK + fp16 2-pass PV)
    {
        dim3 grid(Tn / AT_BQ, Hn, Bn);
        attn_tc<<<grid, 256>>>(qkv_ptr, yhi, ylo);
    }
    // 3) Output projection (fp16 2-pass)
    {
        dim3 grid(Cn / GBN, Mrows / GBM);
        hgemm_2p<<<grid, 256, GEMM_SMEM>>>(yhi, ylo, wph, b_proj,
                                           out, Mrows, Cn, Cn);
    }
}

// round 13
// speedup vs baseline: 1.2219x; 1.2219x over previous
#include <cuda_runtime.h>
#include <cuda_bf16.h>
#include <cuda_fp16.h>
#include <math.h>
#include <stdint.h>

// Problem constants
#define Bn  2
#define Tn  2048
#define Cn  1024
#define Hn  16
#define HDn 64
#define QKV_N (3*Cn)          // 3072
#define Mrows (Bn*Tn)         // 4096

// Scratch (allocation-free: __device__ globals)
__device__ float g_qkv[(size_t)Mrows * QKV_N];
__device__ __half g_xhi[(size_t)Mrows * Cn];
__device__ __half g_xlo[(size_t)Mrows * Cn];
__device__ __half g_wah[(size_t)Cn * QKV_N];     // fp16(w_attn), unsplit
__device__ __half g_wph[(size_t)Cn * Cn];        // fp16(w_proj), unsplit
__device__ __half g_yhi[(size_t)Mrows * Cn];
__device__ __half g_ylo[(size_t)Mrows * Cn];

// ===========================================================================
// fp32 -> fp16 hi/lo split  and  fp32 -> fp16 convert (weights)
// ===========================================================================
__global__ __launch_bounds__(256)
void split2h(const float* __restrict__ src, __half* __restrict__ hi,
             __half* __restrict__ lo, int n4)
{
    int i = blockIdx.x * blockDim.x + threadIdx.x;
    if (i >= n4) return;
    float4 v = ((const float4*)src)[i];
    __half hx = __float2half_rn(v.x), hy = __float2half_rn(v.y);
    __half hz = __float2half_rn(v.z), hw = __float2half_rn(v.w);
    ((__half2*)hi)[2 * i]     = __half2(hx, hy);
    ((__half2*)hi)[2 * i + 1] = __half2(hz, hw);
    ((__half2*)lo)[2 * i] = __half2(
        __float2half_rn(v.x - __half2float(hx)),
        __float2half_rn(v.y - __half2float(hy)));
    ((__half2*)lo)[2 * i + 1] = __half2(
        __float2half_rn(v.z - __half2float(hz)),
        __float2half_rn(v.w - __half2float(hw)));
}

__global__ __launch_bounds__(256)
void conv_h(const float* __restrict__ src, __half* __restrict__ dst, int n4)
{
    int i = blockIdx.x * blockDim.x + threadIdx.x;
    if (i >= n4) return;
    float4 v = ((const float4*)src)[i];
    ((__half2*)dst)[2 * i]     = __floats2half2_rn(v.x, v.y);
    ((__half2*)dst)[2 * i + 1] = __floats2half2_rn(v.z, v.w);
}

// ===========================================================================
// Pipelined fp16 2-pass GEMM (R10 winner, unchanged): C = (Ahi+Alo)@Bh + bias
// ===========================================================================
#define GBM 128
#define GBN 128
#define GBK 32
#define ASTR 40
#define BSTR 136
#define OFF_AHI 0
#define OFF_ALO 10240
#define OFF_BHI 20480
#define STAGE_BYTES 29184
#define GEMM_SMEM (2*STAGE_BYTES)

__device__ __forceinline__ void cpasync16(uint32_t dst, const void* src) {
    asm volatile("cp.async.cg.shared.global [%0], [%1], 16;" :: "r"(dst), "l"(src));
}
__device__ __forceinline__ void ldsm4(uint32_t r[4], uint32_t addr) {
    asm volatile("ldmatrix.sync.aligned.m8n8.x4.shared.b16 {%0,%1,%2,%3}, [%4];"
                 : "=r"(r[0]), "=r"(r[1]), "=r"(r[2]), "=r"(r[3]) : "r"(addr));
}
__device__ __forceinline__ void ldsm4t(uint32_t r[4], uint32_t addr) {
    asm volatile("ldmatrix.sync.aligned.m8n8.x4.trans.shared.b16 {%0,%1,%2,%3}, [%4];"
                 : "=r"(r[0]), "=r"(r[1]), "=r"(r[2]), "=r"(r[3]) : "r"(addr));
}
__device__ __forceinline__ void mma_f16(float d[4], const uint32_t a[4],
                                        uint32_t b0, uint32_t b1) {
    asm volatile(
        "mma.sync.aligned.m16n8k16.row.col.f32.f16.f16.f32 "
        "{%0,%1,%2,%3}, {%4,%5,%6,%7}, {%8,%9}, {%0,%1,%2,%3};"
        : "+f"(d[0]), "+f"(d[1]), "+f"(d[2]), "+f"(d[3])
        : "r"(a[0]), "r"(a[1]), "r"(a[2]), "r"(a[3]), "r"(b0), "r"(b1));
}

__global__ __launch_bounds__(256, 2)
void hgemm_2p(const __half* __restrict__ Ahi_g, const __half* __restrict__ Alo_g,
              const __half* __restrict__ Bh_g,
              const float* __restrict__ bias, float* __restrict__ C,
              int M, int N, int K)
{
    extern __shared__ char gsm[];
    const int tid  = threadIdx.x;
    const int warp = tid >> 5;
    const int lane = tid & 31;
    const int g  = lane >> 2;
    const int tg = lane & 3;

    const int bm = blockIdx.y * GBM;
    const int bn = blockIdx.x * GBN;
    const int warp_m = (warp >> 1) * 32;
    const int warp_n = (warp & 1) * 64;

    const int ar = tid >> 2, ac = (tid & 3) * 8;
    const int br = tid >> 4, bc = (tid & 15) * 8;
    const __half* aih = Ahi_g + (size_t)(bm + ar) * K + ac;
    const __half* ail = Alo_g + (size_t)(bm + ar) * K + ac;
    const __half* bhg = Bh_g  + (size_t)br * N + bn + bc;
    const size_t a64 = (size_t)64 * K;
    const size_t b16 = (size_t)16 * N;

    const uint32_t smb = (uint32_t)__cvta_generic_to_shared(gsm);
    const uint32_t dA  = (uint32_t)(ar * ASTR + ac) * 2;
    const uint32_t dA2 = (uint32_t)((ar + 64) * ASTR + ac) * 2;
    const uint32_t dB  = (uint32_t)(br * BSTR + bc) * 2;
    const uint32_t dB2 = (uint32_t)((br + 16) * BSTR + bc) * 2;

    float acc[2][8][4];
    #pragma unroll
    for (int mt = 0; mt < 2; mt++)
        #pragma unroll
        for (int nt = 0; nt < 8; nt++)
            #pragma unroll
            for (int i = 0; i < 4; i++) acc[mt][nt][i] = 0.f;

    const int NK = K / GBK;

    #define ISSUE_STAGE(s, kit) do {                                         \
        uint32_t so = smb + (uint32_t)(s) * STAGE_BYTES;                     \
        size_t ka = (size_t)(kit) * GBK;                                     \
        size_t kb = (size_t)(kit) * GBK * (size_t)N;                         \
        cpasync16(so + OFF_AHI + dA,  aih + ka);                             \
        cpasync16(so + OFF_AHI + dA2, aih + a64 + ka);                       \
        cpasync16(so + OFF_ALO + dA,  ail + ka);                             \
        cpasync16(so + OFF_ALO + dA2, ail + a64 + ka);                       \
        cpasync16(so + OFF_BHI + dB,  bhg + kb);                             \
        cpasync16(so + OFF_BHI + dB2, bhg + b16 + kb);                       \
        asm volatile("cp.async.commit_group;");                              \
    } while (0)

    ISSUE_STAGE(0, 0);

    const int a_r = lane & 15;
    const int a_c = (lane >> 4) * 8;

    for (int it = 0; it < NK; it++) {
        if (it + 1 < NK) {
            ISSUE_STAGE((it + 1) & 1, it + 1);
            asm volatile("cp.async.wait_group 1;");
        } else {
            asm volatile("cp.async.wait_group 0;");
        }
        __syncthreads();

        const uint32_t sb = smb + (uint32_t)(it & 1) * STAGE_BYTES;
        #pragma unroll
        for (int ks = 0; ks < 2; ks++) {
            const int kk = ks * 16;
            uint32_t ah[2][4], al[2][4];
            #pragma unroll
            for (int mt = 0; mt < 2; mt++) {
                uint32_t off = (uint32_t)((warp_m + mt * 16 + a_r) * ASTR + kk + a_c) * 2;
                ldsm4(ah[mt], sb + OFF_AHI + off);
                ldsm4(al[mt], sb + OFF_ALO + off);
            }
            #pragma unroll
            for (int np = 0; np < 4; np++) {
                uint32_t bh[4];
                uint32_t off = (uint32_t)((kk + a_r) * BSTR + warp_n + np * 16 + a_c) * 2;
                ldsm4t(bh, sb + OFF_BHI + off);
                #pragma unroll
                for (int pass = 0; pass < 2; pass++) {
                    #pragma unroll
                    for (int half = 0; half < 2; half++) {
                        const int nt = np * 2 + half;
                        #pragma unroll
                        for (int mt = 0; mt < 2; mt++) {
                            mma_f16(acc[mt][nt], pass ? al[mt] : ah[mt],
                                    bh[half * 2], bh[half * 2 + 1]);
                        }
                    }
                }
            }
        }
        __syncthreads();
    }

    #pragma unroll
    for (int nt = 0; nt < 8; nt++) {
        const int col = bn + warp_n + nt * 8 + 2 * tg;
        const float2 bs = *(const float2*)&bias[col];
        #pragma unroll
        for (int mt = 0; mt < 2; mt++) {
            const int row0 = bm + warp_m + mt * 16 + g;
            float2 o0 = make_float2(acc[mt][nt][0] + bs.x, acc[mt][nt][1] + bs.y);
            float2 o1 = make_float2(acc[mt][nt][2] + bs.x, acc[mt][nt][3] + bs.y);
            *(float2*)&C[(size_t)row0 * N + col]       = o0;
            *(float2*)&C[(size_t)(row0 + 8) * N + col] = o1;
        }
    }
    #undef ISSUE_STAGE
}

// ===========================================================================
// Flash attention: QK tf32 RNA (exactly as R10), PV fp16 2-pass
// (P split fp16 hi/lo = exact; V plain fp16). 256 threads, BQ=128, BKV=64.
// ===========================================================================
#define AT_BQ   128
#define AT_BKV  64
#define KPAD    68
#define VSTR    72
#define SCALE   0.125f

__device__ __forceinline__ float tf32r(float x) {
    uint32_t u;
    asm("cvt.rna.tf32.f32 %0, %1;" : "=r"(u) : "f"(x));
    return __uint_as_float(u);
}
__device__ __forceinline__ void mma_tf32(float d[4], const uint32_t a[4],
                                         uint32_t b0, uint32_t b1) {
    asm volatile(
        "mma.sync.aligned.m16n8k8.row.col.f32.tf32.tf32.f32 "
        "{%0,%1,%2,%3}, {%4,%5,%6,%7}, {%8,%9}, {%0,%1,%2,%3};"
        : "+f"(d[0]), "+f"(d[1]), "+f"(d[2]), "+f"(d[3])
        : "r"(a[0]), "r"(a[1]), "r"(a[2]), "r"(a[3]), "r"(b0), "r"(b1));
}

__global__ __launch_bounds__(256)
void attn_tc(const float* __restrict__ qkv,
             __half* __restrict__ yhi, __half* __restrict__ ylo)
{
    __shared__ float pool[8704];            // Q staging 128*68; later Ks + Vp
    float*    Ks = pool;                    // 64*68 = 4352 words (tf32 bits)
    uint32_t* Vp = (uint32_t*)pool + AT_BKV * KPAD;   // fp16 pairs: 32*72 words

    const int b = blockIdx.z, h = blockIdx.y;
    const int qtile = gridDim.x - 1 - blockIdx.x;   // heavy tiles first
    const int q0 = qtile * AT_BQ;
    const int tid  = threadIdx.x;
    const int warp = tid >> 5;
    const int lane = tid & 31;
    const int g  = lane >> 2;
    const int tg = lane & 3;

    // ---- stage Q tile (pre-scaled, tf32 RNA bits) ----
    {
        const float* qg = qkv + ((size_t)(b * Tn + q0)) * QKV_N + h * HDn;
        #pragma unroll
        for (int itr = 0; itr < 8; itr++) {
            int f = itr * 256 + tid;
            int r = f >> 4, c = (f & 15) << 2;
            float4 v = *(const float4*)(qg + (size_t)r * QKV_N + c);
            float4 t;
            t.x = tf32r(v.x * SCALE); t.y = tf32r(v.y * SCALE);
            t.z = tf32r(v.z * SCALE); t.w = tf32r(v.w * SCALE);
            *(float4*)&pool[r * KPAD + c] = t;
        }
    }
    __syncthreads();

    uint32_t Aq[8][4];
    {
        const int r0 = warp * 16 + g;
        #pragma unroll
        for (int k = 0; k < 8; k++) {
            Aq[k][0] = __float_as_uint(pool[(r0    ) * KPAD + k * 8 + tg    ]);
            Aq[k][1] = __float_as_uint(pool[(r0 + 8) * KPAD + k * 8 + tg    ]);
            Aq[k][2] = __float_as_uint(pool[(r0    ) * KPAD + k * 8 + tg + 4]);
            Aq[k][3] = __float_as_uint(pool[(r0 + 8) * KPAD + k * 8 + tg + 4]);
        }
    }
    __syncthreads();

    float O[8][4];
    #pragma unroll
    for (int nt = 0; nt < 8; nt++)
        #pragma unroll
        for (int i = 0; i < 4; i++) O[nt][i] = 0.f;

    float m0 = -INFINITY, m1 = -INFINITY;
    float l0 = 0.f, l1 = 0.f;

    const int qi0 = q0 + warp * 16 + g;
    const int qi1 = qi0 + 8;
    const int w_qmax = q0 + warp * 16 + 15;
    const int w_qmin = q0 + warp * 16;

    for (int kt = 0; kt < q0 + AT_BQ; kt += AT_BKV) {
        // ---- stage K (tf32 RNA) — unchanged from R10 ----
        {
            const float* kg = qkv + ((size_t)(b * Tn + kt)) * QKV_N + Cn + h * HDn;
            #pragma unroll
            for (int itr = 0; itr < 4; itr++) {
                int f = itr * 256 + tid;
                int r = f >> 4, c = (f & 15) << 2;
                float4 kv4 = *(const float4*)(kg + (size_t)r * QKV_N + c);
                float4 tk;
                tk.x = tf32r(kv4.x); tk.y = tf32r(kv4.y);
                tk.z = tf32r(kv4.z); tk.w = tf32r(kv4.w);
                *(float4*)&Ks[r * KPAD + c] = tk;
            }
        }
        // ---- stage V as fp16 row-pair-packed (single buffer) ----
        {
            const float* vg = qkv + ((size_t)(b * Tn + kt)) * QKV_N + 2 * Cn + h * HDn;
            #pragma unroll
            for (int itr = 0; itr < 2; itr++) {
                int f = itr * 256 + tid;
                int p  = f >> 4;
                int c4 = (f & 15) * 4;
                const float* r0p = vg + (size_t)(2 * p) * QKV_N + c4;
                float4 v0 = *(const float4*)r0p;
                float4 v1 = *(const float4*)(r0p + QKV_N);
                __half2 h0 = __floats2half2_rn(v0.x, v1.x);
                __half2 h1 = __floats2half2_rn(v0.y, v1.y);
                __half2 h2 = __floats2half2_rn(v0.z, v1.z);
                __half2 h3 = __floats2half2_rn(v0.w, v1.w);
                *(uint4*)&Vp[p * VSTR + c4] = make_uint4(
                    *(uint32_t*)&h0, *(uint32_t*)&h1,
                    *(uint32_t*)&h2, *(uint32_t*)&h3);
            }
        }
        __syncthreads();

        if (kt <= w_qmax) {
            // ---- S = Q @ K^T (tf32, k-major, scale pre-folded) — as R10 ----
            float S[8][4];
            #pragma unroll
            for (int nt = 0; nt < 8; nt++) {
                S[nt][0] = S[nt][1] = S[nt][2] = S[nt][3] = 0.f;
            }
            #pragma unroll
            for (int k = 0; k < 8; k++) {
                #pragma unroll
                for (int nt = 0; nt < 8; nt++) {
                    uint32_t b0 = __float_as_uint(Ks[(nt * 8 + g) * KPAD + k * 8 + tg    ]);
                    uint32_t b1 = __float_as_uint(Ks[(nt * 8 + g) * KPAD + k * 8 + tg + 4]);
                    mma_tf32(S[nt], Aq[k], b0, b1);
                }
            }

            const bool need_mask = (kt + AT_BKV - 1 > w_qmin);
            if (need_mask) {
                #pragma unroll
                for (int nt = 0; nt < 8; nt++) {
                    int j0 = kt + nt * 8 + 2 * tg;
                    int j1 = j0 + 1;
                    if (j0 > qi0) S[nt][0] = -INFINITY;
                    if (j1 > qi0) S[nt][1] = -INFINITY;
                    if (j0 > qi1) S[nt][2] = -INFINITY;
                    if (j1 > qi1) S[nt][3] = -INFINITY;
                }
            }

            // ---- online softmax (unchanged) ----
            float mc0 = -INFINITY, mc1 = -INFINITY;
            #pragma unroll
            for (int nt = 0; nt < 8; nt++) {
                mc0 = fmaxf(mc0, fmaxf(S[nt][0], S[nt][1]));
                mc1 = fmaxf(mc1, fmaxf(S[nt][2], S[nt][3]));
            }
            mc0 = fmaxf(mc0, __shfl_xor_sync(0xffffffffu, mc0, 1));
            mc0 = fmaxf(mc0, __shfl_xor_sync(0xffffffffu, mc0, 2));
            mc1 = fmaxf(mc1, __shfl_xor_sync(0xffffffffu, mc1, 1));
            mc1 = fmaxf(mc1, __shfl_xor_sync(0xffffffffu, mc1, 2));

            float mn0 = fmaxf(m0, mc0);
            float mn1 = fmaxf(m1, mc1);
            float corr0 = __expf(m0 - mn0);
            float corr1 = __expf(m1 - mn1);
            m0 = mn0; m1 = mn1;

            float ps0 = 0.f, ps1 = 0.f;
            #pragma unroll
            for (int nt = 0; nt < 8; nt++) {
                S[nt][0] = __expf(S[nt][0] - mn0);
                S[nt][1] = __expf(S[nt][1] - mn0);
                S[nt][2] = __expf(S[nt][2] - mn1);
                S[nt][3] = __expf(S[nt][3] - mn1);
                ps0 += S[nt][0] + S[nt][1];
                ps1 += S[nt][2] + S[nt][3];
            }
            ps0 += __shfl_xor_sync(0xffffffffu, ps0, 1);
            ps0 += __shfl_xor_sync(0xffffffffu, ps0, 2);
            ps1 += __shfl_xor_sync(0xffffffffu, ps1, 1);
            ps1 += __shfl_xor_sync(0xffffffffu, ps1, 2);
            l0 = l0 * corr0 + ps0;
            l1 = l1 * corr1 + ps1;

            #pragma unroll
            for (int nt = 0; nt < 8; nt++) {
                O[nt][0] *= corr0; O[nt][1] *= corr0;
                O[nt][2] *= corr1; O[nt][3] *= corr1;
            }

            // ---- O += P @ V, fp16 2-pass (P hi/lo exact, V fp16) ----
            #pragma unroll
            for (int s = 0; s < 4; s++) {
                uint32_t aph[4], apl[4];
                const float pv[8] = {
                    S[2*s  ][0], S[2*s  ][1], S[2*s  ][2], S[2*s  ][3],
                    S[2*s+1][0], S[2*s+1][1], S[2*s+1][2], S[2*s+1][3]
                };
                #pragma unroll
                for (int q = 0; q < 4; q++) {
                    __half2 hp = __floats2half2_rn(pv[2*q], pv[2*q+1]);
                    aph[q] = *(uint32_t*)&hp;
                    float2 hf = __half22float2(hp);
                    __half2 lp = __floats2half2_rn(pv[2*q] - hf.x, pv[2*q+1] - hf.y);
                    apl[q] = *(uint32_t*)&lp;
                }
                const int pr0 = (8 * s + tg) * VSTR;
                const int pr1 = (8 * s + tg + 4) * VSTR;
                #pragma unroll
                for (int dd = 0; dd < 8; dd++) {
                    const int dc = dd * 8 + g;
                    uint32_t b0 = Vp[pr0 + dc];
                    uint32_t b1 = Vp[pr1 + dc];
                    mma_f16(O[dd], aph, b0, b1);
                    mma_f16(O[dd], apl, b0, b1);
                }
            }
        }
        __syncthreads();
    }

    // ---- finalize: divide by l, split to fp16 hi/lo, store ----
    const float inv0 = 1.f / l0;
    const float inv1 = 1.f / l1;
    const size_t row0 = (size_t)(b * Tn + qi0) * Cn + h * HDn;
    const size_t row1 = (size_t)(b * Tn + qi1) * Cn + h * HDn;
    #pragma unroll
    for (int nt = 0; nt < 8; nt++) {
        int c = nt * 8 + 2 * tg;
        float v00 = O[nt][0] * inv0, v01 = O[nt][1] * inv0;
        float v10 = O[nt][2] * inv1, v11 = O[nt][3] * inv1;
        __half h00 = __float2half_rn(v00), h01 = __float2half_rn(v01);
        __half h10 = __float2half_rn(v10), h11 = __float2half_rn(v11);
        *(__half2*)&yhi[row0 + c] = __half2(h00, h01);
        *(__half2*)&yhi[row1 + c] = __half2(h10, h11);
        *(__half2*)&ylo[row0 + c] = __half2(
            __float2half_rn(v00 - __half2float(h00)),
            __float2half_rn(v01 - __half2float(h01)));
        *(__half2*)&ylo[row1 + c] = __half2(
            __float2half_rn(v10 - __half2float(h10)),
            __float2half_rn(v11 - __half2float(h11)));
    }
}

// ---------------------------------------------------------------------------
// Launch
// ---------------------------------------------------------------------------
extern "C" void kernel_launch(void* const* d_in, const int* in_sizes, int n_in,
                              void* d_out, int out_size)
{
    const float* x      = (const float*)d_in[0];
    const float* w_attn = (const float*)d_in[1];
    const float* b_attn = (const float*)d_in[2];
    const float* w_proj = (const float*)d_in[3];
    const float* b_proj = (const float*)d_in[4];
    float* out = (float*)d_out;

    float* qkv_ptr; __half *xhi, *xlo, *wah, *wph, *yhi, *ylo;
    cudaGetSymbolAddress((void**)&qkv_ptr, g_qkv);
    cudaGetSymbolAddress((void**)&xhi, g_xhi);
    cudaGetSymbolAddress((void**)&xlo, g_xlo);
    cudaGetSymbolAddress((void**)&wah, g_wah);
    cudaGetSymbolAddress((void**)&wph, g_wph);
    cudaGetSymbolAddress((void**)&yhi, g_yhi);
    cudaGetSymbolAddress((void**)&ylo, g_ylo);

    cudaFuncSetAttribute(hgemm_2p, cudaFuncAttributeMaxDynamicSharedMemorySize, GEMM_SMEM);

    // 0) split x (hi/lo fp16); convert weights to fp16
    {
        int n4;
        n4 = (Mrows * Cn) / 4;
        split2h<<<(n4 + 255) / 256, 256>>>(x, xhi, xlo, n4);
        n4 = (Cn * QKV_N) / 4;
        conv_h<<<(n4 + 255) / 256, 256>>>(w_attn, wah, n4);
        n4 = (Cn * Cn) / 4;
        conv_h<<<(n4 + 255) / 256, 256>>>(w_proj, wph, n4);
    }
    // 1) QKV projection (fp16 2-pass)
    {
        dim3 grid(QKV_N / GBN, Mrows / GBM);
        hgemm_2p<<<grid, 256, GEMM_SMEM>>>(xhi, xlo, wah, b_attn,
                                           qkv_ptr, Mrows, QKV_N, Cn);
    }
    // 2) Causal attention (tf32 QK as R10 + fp16 2-pass PV)
    {
        dim3 grid(Tn / AT_BQ, Hn, Bn);
        attn_tc<<<grid, 256>>>(qkv_ptr, yhi, ylo);
    }
    // 3) Output projection (fp16 2-pass)
    {
        dim3 grid(Cn / GBN, Mrows / GBM);
        hgemm_2p<<<grid, 256, GEMM_SMEM>>>(yhi, ylo, wph, b_proj,
                                           out, Mrows, Cn, Cn);
    }
}

// round 14
// speedup vs baseline: 1.4069x; 1.1514x over previous
#include <cuda_runtime.h>
#include <cuda_bf16.h>
#include <cuda_fp16.h>
#include <math.h>
#include <stdint.h>

// Problem constants
#define Bn  2
#define Tn  2048
#define Cn  1024
#define Hn  16
#define HDn 64
#define QKV_N (3*Cn)          // 3072
#define Mrows (Bn*Tn)         // 4096
#define SCALE 0.125f

// Scratch (allocation-free: __device__ globals)
__device__ float  g_q [(size_t)Bn * Hn * Tn * HDn];       // tf32(q*scale), head-contig
__device__ float  g_k [(size_t)Bn * Hn * Tn * HDn];       // tf32(k), head-contig
__device__ __half g_vp[(size_t)Bn * Hn * (Tn/2) * 2 * HDn]; // fp16 V pair-packed
__device__ __half g_xhi[(size_t)Mrows * Cn];
__device__ __half g_xlo[(size_t)Mrows * Cn];
__device__ __half g_wah[(size_t)Cn * QKV_N];
__device__ __half g_wph[(size_t)Cn * Cn];
__device__ __half g_yhi[(size_t)Mrows * Cn];
__device__ __half g_ylo[(size_t)Mrows * Cn];

// ===========================================================================
// helpers
// ===========================================================================
__device__ __forceinline__ float tf32r(float x) {
    uint32_t u;
    asm("cvt.rna.tf32.f32 %0, %1;" : "=r"(u) : "f"(x));
    return __uint_as_float(u);
}
__device__ __forceinline__ void cpasync16(uint32_t dst, const void* src) {
    asm volatile("cp.async.cg.shared.global [%0], [%1], 16;" :: "r"(dst), "l"(src));
}
__device__ __forceinline__ void ldsm4(uint32_t r[4], uint32_t addr) {
    asm volatile("ldmatrix.sync.aligned.m8n8.x4.shared.b16 {%0,%1,%2,%3}, [%4];"
                 : "=r"(r[0]), "=r"(r[1]), "=r"(r[2]), "=r"(r[3]) : "r"(addr));
}
__device__ __forceinline__ void ldsm4t(uint32_t r[4], uint32_t addr) {
    asm volatile("ldmatrix.sync.aligned.m8n8.x4.trans.shared.b16 {%0,%1,%2,%3}, [%4];"
                 : "=r"(r[0]), "=r"(r[1]), "=r"(r[2]), "=r"(r[3]) : "r"(addr));
}
__device__ __forceinline__ void mma_f16(float d[4], const uint32_t a[4],
                                        uint32_t b0, uint32_t b1) {
    asm volatile(
        "mma.sync.aligned.m16n8k16.row.col.f32.f16.f16.f32 "
        "{%0,%1,%2,%3}, {%4,%5,%6,%7}, {%8,%9}, {%0,%1,%2,%3};"
        : "+f"(d[0]), "+f"(d[1]), "+f"(d[2]), "+f"(d[3])
        : "r"(a[0]), "r"(a[1]), "r"(a[2]), "r"(a[3]), "r"(b0), "r"(b1));
}
__device__ __forceinline__ void mma_tf32(float d[4], const uint32_t a[4],
                                         uint32_t b0, uint32_t b1) {
    asm volatile(
        "mma.sync.aligned.m16n8k8.row.col.f32.tf32.tf32.f32 "
        "{%0,%1,%2,%3}, {%4,%5,%6,%7}, {%8,%9}, {%0,%1,%2,%3};"
        : "+f"(d[0]), "+f"(d[1]), "+f"(d[2]), "+f"(d[3])
        : "r"(a[0]), "r"(a[1]), "r"(a[2]), "r"(a[3]), "r"(b0), "r"(b1));
}

// ===========================================================================
// fp32 -> fp16 hi/lo split  and  fp32 -> fp16 convert (weights)
// ===========================================================================
__global__ __launch_bounds__(256)
void split2h(const float* __restrict__ src, __half* __restrict__ hi,
             __half* __restrict__ lo, int n4)
{
    int i = blockIdx.x * blockDim.x + threadIdx.x;
    if (i >= n4) return;
    float4 v = ((const float4*)src)[i];
    __half hx = __float2half_rn(v.x), hy = __float2half_rn(v.y);
    __half hz = __float2half_rn(v.z), hw = __float2half_rn(v.w);
    ((__half2*)hi)[2 * i]     = __half2(hx, hy);
    ((__half2*)hi)[2 * i + 1] = __half2(hz, hw);
    ((__half2*)lo)[2 * i] = __half2(
        __float2half_rn(v.x - __half2float(hx)),
        __float2half_rn(v.y - __half2float(hy)));
    ((__half2*)lo)[2 * i + 1] = __half2(
        __float2half_rn(v.z - __half2float(hz)),
        __float2half_rn(v.w - __half2float(hw)));
}

__global__ __launch_bounds__(256)
void conv_h(const float* __restrict__ src, __half* __restrict__ dst, int n4)
{
    int i = blockIdx.x * blockDim.x + threadIdx.x;
    if (i >= n4) return;
    float4 v = ((const float4*)src)[i];
    ((__half2*)dst)[2 * i]     = __floats2half2_rn(v.x, v.y);
    ((__half2*)dst)[2 * i + 1] = __floats2half2_rn(v.z, v.w);
}

// ===========================================================================
// GEMM mainloop shared macros (fp16 2-pass, R10 winner structure)
// ===========================================================================
#define GBM 128
#define GBN 128
#define GBK 32
#define ASTR 40
#define BSTR 136
#define OFF_AHI 0
#define OFF_ALO 10240
#define OFF_BHI 20480
#define STAGE_BYTES 29184
#define GEMM_SMEM (2*STAGE_BYTES)

#define GEMM_PROLOGUE()                                                      \
    extern __shared__ char gsm[];                                            \
    const int tid  = threadIdx.x;                                            \
    const int warp = tid >> 5;                                               \
    const int lane = tid & 31;                                               \
    const int g  = lane >> 2;                                                \
    const int tg = lane & 3;                                                 \
    const int bm = blockIdx.y * GBM;                                         \
    const int bn = blockIdx.x * GBN;                                         \
    const int warp_m = (warp >> 1) * 32;                                     \
    const int warp_n = (warp & 1) * 64;                                      \
    const int ar = tid >> 2, ac = (tid & 3) * 8;                             \
    const int br = tid >> 4, bc = (tid & 15) * 8;                            \
    const __half* aih = Ahi_g + (size_t)(bm + ar) * K + ac;                  \
    const __half* ail = Alo_g + (size_t)(bm + ar) * K + ac;                  \
    const __half* bhg = Bh_g  + (size_t)br * N + bn + bc;                    \
    const size_t a64 = (size_t)64 * K;                                       \
    const size_t b16 = (size_t)16 * N;                                       \
    const uint32_t smb = (uint32_t)__cvta_generic_to_shared(gsm);            \
    const uint32_t dA  = (uint32_t)(ar * ASTR + ac) * 2;                     \
    const uint32_t dA2 = (uint32_t)((ar + 64) * ASTR + ac) * 2;              \
    const uint32_t dB  = (uint32_t)(br * BSTR + bc) * 2;                     \
    const uint32_t dB2 = (uint32_t)((br + 16) * BSTR + bc) * 2;              \
    float acc[2][8][4];                                                      \
    _Pragma("unroll")                                                        \
    for (int mt = 0; mt < 2; mt++)                                           \
        _Pragma("unroll")                                                    \
        for (int nt = 0; nt < 8; nt++)                                       \
            _Pragma("unroll")                                                \
            for (int i = 0; i < 4; i++) acc[mt][nt][i] = 0.f;                \
    const int NK = K / GBK;

#define ISSUE_STAGE(s, kit) do {                                             \
    uint32_t so = smb + (uint32_t)(s) * STAGE_BYTES;                         \
    size_t ka = (size_t)(kit) * GBK;                                         \
    size_t kb = (size_t)(kit) * GBK * (size_t)N;                             \
    cpasync16(so + OFF_AHI + dA,  aih + ka);                                 \
    cpasync16(so + OFF_AHI + dA2, aih + a64 + ka);                           \
    cpasync16(so + OFF_ALO + dA,  ail + ka);                                 \
    cpasync16(so + OFF_ALO + dA2, ail + a64 + ka);                           \
    cpasync16(so + OFF_BHI + dB,  bhg + kb);                                 \
    cpasync16(so + OFF_BHI + dB2, bhg + b16 + kb);                           \
    asm volatile("cp.async.commit_group;");                                  \
} while (0)

#define GEMM_MAINLOOP()                                                      \
    ISSUE_STAGE(0, 0);                                                       \
    const int a_r = lane & 15;                                               \
    const int a_c = (lane >> 4) * 8;                                         \
    for (int it = 0; it < NK; it++) {                                        \
        if (it + 1 < NK) {                                                   \
            ISSUE_STAGE((it + 1) & 1, it + 1);                               \
            asm volatile("cp.async.wait_group 1;");                          \
        } else {                                                             \
            asm volatile("cp.async.wait_group 0;");                          \
        }                                                                    \
        __syncthreads();                                                     \
        const uint32_t sb = smb + (uint32_t)(it & 1) * STAGE_BYTES;          \
        _Pragma("unroll")                                                    \
        for (int ks = 0; ks < 2; ks++) {                                     \
            const int kk = ks * 16;                                          \
            uint32_t ah[2][4], al[2][4];                                     \
            _Pragma("unroll")                                                \
            for (int mt = 0; mt < 2; mt++) {                                 \
                uint32_t off = (uint32_t)((warp_m + mt * 16 + a_r) * ASTR    \
                                          + kk + a_c) * 2;                   \
                ldsm4(ah[mt], sb + OFF_AHI + off);                           \
                ldsm4(al[mt], sb + OFF_ALO + off);                           \
            }                                                                \
            _Pragma("unroll")                                                \
            for (int np = 0; np < 4; np++) {                                 \
                uint32_t bh[4];                                              \
                uint32_t off = (uint32_t)((kk + a_r) * BSTR + warp_n         \
                                          + np * 16 + a_c) * 2;              \
                ldsm4t(bh, sb + OFF_BHI + off);                              \
                _Pragma("unroll")                                            \
                for (int pass = 0; pass < 2; pass++) {                       \
                    _Pragma("unroll")                                        \
                    for (int half = 0; half < 2; half++) {                   \
                        const int nt = np * 2 + half;                        \
                        _Pragma("unroll")                                    \
                        for (int mt = 0; mt < 2; mt++) {                     \
                            mma_f16(acc[mt][nt], pass ? al[mt] : ah[mt],     \
                                    bh[half * 2], bh[half * 2 + 1]);         \
                        }                                                    \
                    }                                                        \
                }                                                            \
            }                                                                \
        }                                                                    \
        __syncthreads();                                                     \
    }

// ---------------------------------------------------------------------------
// Generic GEMM (used for proj): C fp32 row-major + bias
// ---------------------------------------------------------------------------
__global__ __launch_bounds__(256, 2)
void hgemm_2p(const __half* __restrict__ Ahi_g, const __half* __restrict__ Alo_g,
              const __half* __restrict__ Bh_g,
              const float* __restrict__ bias, float* __restrict__ C,
              int M, int N, int K)
{
    GEMM_PROLOGUE();
    GEMM_MAINLOOP();
    #pragma unroll
    for (int nt = 0; nt < 8; nt++) {
        const int col = bn + warp_n + nt * 8 + 2 * tg;
        const float2 bs = *(const float2*)&bias[col];
        #pragma unroll
        for (int mt = 0; mt < 2; mt++) {
            const int row0 = bm + warp_m + mt * 16 + g;
            float2 o0 = make_float2(acc[mt][nt][0] + bs.x, acc[mt][nt][1] + bs.y);
            float2 o1 = make_float2(acc[mt][nt][2] + bs.x, acc[mt][nt][3] + bs.y);
            *(float2*)&C[(size_t)row0 * N + col]       = o0;
            *(float2*)&C[(size_t)(row0 + 8) * N + col] = o1;
        }
    }
}

// ---------------------------------------------------------------------------
// QKV GEMM: routes output to head-contiguous Q (tf32*scale), K (tf32),
// V (fp16 pair-packed) buffers. N = 3072.
// ---------------------------------------------------------------------------
__global__ __launch_bounds__(256, 2)
void hgemm_qkv(const __half* __restrict__ Ahi_g, const __half* __restrict__ Alo_g,
               const __half* __restrict__ Bh_g,
               const float* __restrict__ bias,
               float* __restrict__ Q, float* __restrict__ Kd,
               __half* __restrict__ Vp,
               int M, int N, int K)
{
    GEMM_PROLOGUE();
    GEMM_MAINLOOP();
    #pragma unroll
    for (int nt = 0; nt < 8; nt++) {
        const int col = bn + warp_n + nt * 8 + 2 * tg;      // col, col+1
        const float2 bs = *(const float2*)&bias[col];
        const int sec = col >> 10;            // 0=Q 1=K 2=V
        const int hh  = (col & 1023) >> 6;
        const int dd  = col & 63;
        #pragma unroll
        for (int mt = 0; mt < 2; mt++) {
            const int r0 = bm + warp_m + mt * 16 + g;
            #pragma unroll
            for (int rr = 0; rr < 2; rr++) {
                const int row = r0 + rr * 8;
                const int bb = row >> 11;
                const int tt = row & 2047;
                float v0 = acc[mt][nt][2 * rr]     + bs.x;
                float v1 = acc[mt][nt][2 * rr + 1] + bs.y;
                if (sec == 0) {
                    float* p = Q + (((size_t)(bb * Hn + hh) * Tn + tt) << 6) + dd;
                    *(float2*)p = make_float2(tf32r(v0 * SCALE), tf32r(v1 * SCALE));
                } else if (sec == 1) {
                    float* p = Kd + (((size_t)(bb * Hn + hh) * Tn + tt) << 6) + dd;
                    *(float2*)p = make_float2(tf32r(v0), tf32r(v1));
                } else {
                    __half* p = Vp + (((size_t)(bb * Hn + hh) * (Tn / 2)
                                       + (tt >> 1)) << 7) + (tt & 1);
                    p[dd * 2]       = __float2half_rn(v0);
                    p[(dd + 1) * 2] = __float2half_rn(v1);
                }
            }
        }
    }
}

// ===========================================================================
// Flash attention v5: inputs pre-converted by QKV epilogue.
// K: tf32-bits fp32 (cp.async direct). V: fp16 pair-packed (cp.async direct).
// Triple-buffered, ONE __syncthreads per tile, zero staging conversion.
// ===========================================================================
#define AT_BQ   128
#define AT_BKV  64
#define KSTR    68
#define VSTR    72
#define KBUF_W  (AT_BKV * KSTR)    // 4352 words
#define VBUF_W  (32 * VSTR)        // 2304 words
#define AT_SMEM ((3 * KBUF_W + 3 * VBUF_W) * 4)   // 79872 bytes

__global__ __launch_bounds__(256)
void attn_tc(const float* __restrict__ gq, const float* __restrict__ gk,
             const __half* __restrict__ gvp,
             __half* __restrict__ yhi, __half* __restrict__ ylo)
{
    extern __shared__ float pool[];   // [K0|K1|K2|V0|V1|V2]; Q staging reuses front

    const int b = blockIdx.z, h = blockIdx.y;
    const int qtile = gridDim.x - 1 - blockIdx.x;
    const int q0 = qtile * AT_BQ;
    const int tid  = threadIdx.x;
    const int warp = tid >> 5;
    const int lane = tid & 31;
    const int g  = lane >> 2;
    const int tg = lane & 3;

    const float*  qb  = gq  + ((size_t)(b * Hn + h) * Tn) * HDn;
    const float*  kb  = gk  + ((size_t)(b * Hn + h) * Tn) * HDn;
    const __half* vb  = gvp + ((size_t)(b * Hn + h) * (Tn / 2)) * 2 * HDn;

    // ---- stage Q (dense 256B rows, already tf32*scale) ----
    {
        const float* qg = qb + (size_t)q0 * HDn;
        #pragma unroll
        for (int itr = 0; itr < 8; itr++) {
            int f = itr * 256 + tid;
            int r = f >> 4, c = (f & 15) << 2;
            *(float4*)&pool[r * KSTR + c] = *(const float4*)(qg + r * HDn + c);
        }
    }
    __syncthreads();

    uint32_t Aq[8][4];
    {
        const int r0 = warp * 16 + g;
        #pragma unroll
        for (int k = 0; k < 8; k++) {
            Aq[k][0] = __float_as_uint(pool[(r0    ) * KSTR + k * 8 + tg    ]);
            Aq[k][1] = __float_as_uint(pool[(r0 + 8) * KSTR + k * 8 + tg    ]);
            Aq[k][2] = __float_as_uint(pool[(r0    ) * KSTR + k * 8 + tg + 4]);
            Aq[k][3] = __float_as_uint(pool[(r0 + 8) * KSTR + k * 8 + tg + 4]);
        }
    }
    __syncthreads();

    // cp.async geometry
    const uint32_t smb = (uint32_t)__cvta_generic_to_shared(pool);
    const int kr = tid >> 2;               // base K row for i=0 (r = kr + 64*? no)
    // K: 4 granules/thread, V: 2 granules/thread
    int krow[4]; uint32_t kdst[4];
    #pragma unroll
    for (int i = 0; i < 4; i++) {
        int f = i * 256 + tid;
        krow[i] = f >> 4;
        kdst[i] = (uint32_t)(krow[i] * KSTR + (f & 15) * 4) * 4;
    }
    int vrow[2]; uint32_t vdst[2]; int vcol[2];
    #pragma unroll
    for (int i = 0; i < 2; i++) {
        int f = i * 256 + tid;
        vrow[i] = f >> 4;                  // pair row 0..31
        vcol[i] = (f & 15) * 8;            // half offset (16B granule)
        vdst[i] = (uint32_t)(vrow[i] * VSTR + (f & 15) * 4) * 4;
    }

    const int NT = (q0 + AT_BQ) / AT_BKV;

    #define AT_ISSUE(tile, s) do {                                            \
        const uint32_t _ks = smb + (uint32_t)(s) * (KBUF_W * 4);              \
        const uint32_t _vs = smb + (uint32_t)(3 * KBUF_W + (s) * VBUF_W) * 4; \
        const int _kt = (tile) * AT_BKV;                                      \
        _Pragma("unroll")                                                     \
        for (int _i = 0; _i < 4; _i++)                                        \
            cpasync16(_ks + kdst[_i],                                         \
                      kb + (size_t)(_kt + krow[_i]) * HDn                     \
                         + ((kdst[_i] >> 2) % KSTR));                         \
        _Pragma("unroll")                                                     \
        for (int _i = 0; _i < 2; _i++)                                        \
            cpasync16(_vs + vdst[_i],                                         \
                      vb + (size_t)(_kt / 2 + vrow[_i]) * 2 * HDn + vcol[_i]);\
        asm volatile("cp.async.commit_group;");                               \
    } while (0)

    AT_ISSUE(0, 0);
    if (NT > 1) AT_ISSUE(1, 1);

    float O[8][4];
    #pragma unroll
    for (int nt = 0; nt < 8; nt++)
        #pragma unroll
        for (int i = 0; i < 4; i++) O[nt][i] = 0.f;

    float m0 = -INFINITY, m1 = -INFINITY;
    float l0 = 0.f, l1 = 0.f;

    const int qi0 = q0 + warp * 16 + g;
    const int qi1 = qi0 + 8;
    const int w_qmax = q0 + warp * 16 + 15;
    const int w_qmin = q0 + warp * 16;

    for (int t = 0; t < NT; t++) {
        if (t + 1 < NT) asm volatile("cp.async.wait_group 1;");
        else            asm volatile("cp.async.wait_group 0;");
        __syncthreads();
        if (t + 2 < NT) AT_ISSUE(t + 2, (t + 2) % 3);

        const int kt = t * AT_BKV;
        const float*    Ks = pool + (t % 3) * KBUF_W;
        const uint32_t* Vp = (const uint32_t*)(pool + 3 * KBUF_W + (t % 3) * VBUF_W);

        if (kt <= w_qmax) {
            // ---- S = Q @ K^T (operands pre-tf32) ----
            float S[8][4];
            #pragma unroll
            for (int nt = 0; nt < 8; nt++) {
                S[nt][0] = S[nt][1] = S[nt][2] = S[nt][3] = 0.f;
            }
            #pragma unroll
            for (int k = 0; k < 8; k++) {
                #pragma unroll
                for (int nt = 0; nt < 8; nt++) {
                    uint32_t b0 = __float_as_uint(Ks[(nt * 8 + g) * KSTR + k * 8 + tg    ]);
                    uint32_t b1 = __float_as_uint(Ks[(nt * 8 + g) * KSTR + k * 8 + tg + 4]);
                    mma_tf32(S[nt], Aq[k], b0, b1);
                }
            }

            const bool need_mask = (kt + AT_BKV - 1 > w_qmin);
            if (need_mask) {
                #pragma unroll
                for (int nt = 0; nt < 8; nt++) {
                    int j0 = kt + nt * 8 + 2 * tg;
                    int j1 = j0 + 1;
                    if (j0 > qi0) S[nt][0] = -INFINITY;
                    if (j1 > qi0) S[nt][1] = -INFINITY;
                    if (j0 > qi1) S[nt][2] = -INFINITY;
                    if (j1 > qi1) S[nt][3] = -INFINITY;
                }
            }

            // ---- online softmax ----
            float mc0 = -INFINITY, mc1 = -INFINITY;
            #pragma unroll
            for (int nt = 0; nt < 8; nt++) {
                mc0 = fmaxf(mc0, fmaxf(S[nt][0], S[nt][1]));
                mc1 = fmaxf(mc1, fmaxf(S[nt][2], S[nt][3]));
            }
            mc0 = fmaxf(mc0, __shfl_xor_sync(0xffffffffu, mc0, 1));
            mc0 = fmaxf(mc0, __shfl_xor_sync(0xffffffffu, mc0, 2));
            mc1 = fmaxf(mc1, __shfl_xor_sync(0xffffffffu, mc1, 1));
            mc1 = fmaxf(mc1, __shfl_xor_sync(0xffffffffu, mc1, 2));

            float mn0 = fmaxf(m0, mc0);
            float mn1 = fmaxf(m1, mc1);
            float corr0 = __expf(m0 - mn0);
            float corr1 = __expf(m1 - mn1);
            m0 = mn0; m1 = mn1;

            float ps0 = 0.f, ps1 = 0.f;
            #pragma unroll
            for (int nt = 0; nt < 8; nt++) {
                S[nt][0] = __expf(S[nt][0] - mn0);
                S[nt][1] = __expf(S[nt][1] - mn0);
                S[nt][2] = __expf(S[nt][2] - mn1);
                S[nt][3] = __expf(S[nt][3] - mn1);
                ps0 += S[nt][0] + S[nt][1];
                ps1 += S[nt][2] + S[nt][3];
            }
            ps0 += __shfl_xor_sync(0xffffffffu, ps0, 1);
            ps0 += __shfl_xor_sync(0xffffffffu, ps0, 2);
            ps1 += __shfl_xor_sync(0xffffffffu, ps1, 1);
            ps1 += __shfl_xor_sync(0xffffffffu, ps1, 2);
            l0 = l0 * corr0 + ps0;
            l1 = l1 * corr1 + ps1;

            #pragma unroll
            for (int nt = 0; nt < 8; nt++) {
                O[nt][0] *= corr0; O[nt][1] *= corr0;
                O[nt][2] *= corr1; O[nt][3] *= corr1;
            }

            // ---- O += P @ V, fp16 2-pass (P hi/lo exact, V fp16) ----
            #pragma unroll
            for (int s = 0; s < 4; s++) {
                uint32_t aph[4], apl[4];
                const float pv[8] = {
                    S[2*s  ][0], S[2*s  ][1], S[2*s  ][2], S[2*s  ][3],
                    S[2*s+1][0], S[2*s+1][1], S[2*s+1][2], S[2*s+1][3]
                };
                #pragma unroll
                for (int q = 0; q < 4; q++) {
                    __half2 hp = __floats2half2_rn(pv[2*q], pv[2*q+1]);
                    aph[q] = *(uint32_t*)&hp;
                    float2 hf = __half22float2(hp);
                    __half2 lp = __floats2half2_rn(pv[2*q] - hf.x, pv[2*q+1] - hf.y);
                    apl[q] = *(uint32_t*)&lp;
                }
                const int pr0 = (8 * s + tg) * VSTR;
                const int pr1 = (8 * s + tg + 4) * VSTR;
                #pragma unroll
                for (int dd = 0; dd < 8; dd++) {
                    const int dc = dd * 8 + g;
                    uint32_t b0 = Vp[pr0 + dc];
                    uint32_t b1 = Vp[pr1 + dc];
                    mma_f16(O[dd], aph, b0, b1);
                    mma_f16(O[dd], apl, b0, b1);
                }
            }
        }
    }
    #undef AT_ISSUE

    // ---- finalize: divide by l, split to fp16 hi/lo, store ----
    const float inv0 = 1.f / l0;
    const float inv1 = 1.f / l1;
    const size_t row0 = (size_t)(b * Tn + qi0) * Cn + h * HDn;
    const size_t row1 = (size_t)(b * Tn + qi1) * Cn + h * HDn;
    #pragma unroll
    for (int nt = 0; nt < 8; nt++) {
        int c = nt * 8 + 2 * tg;
        float v00 = O[nt][0] * inv0, v01 = O[nt][1] * inv0;
        float v10 = O[nt][2] * inv1, v11 = O[nt][3] * inv1;
        __half h00 = __float2half_rn(v00), h01 = __float2half_rn(v01);
        __half h10 = __float2half_rn(v10), h11 = __float2half_rn(v11);
        *(__half2*)&yhi[row0 + c] = __half2(h00, h01);
        *(__half2*)&yhi[row1 + c] = __half2(h10, h11);
        *(__half2*)&ylo[row0 + c] = __half2(
            __float2half_rn(v00 - __half2float(h00)),
            __float2half_rn(v01 - __half2float(h01)));
        *(__half2*)&ylo[row1 + c] = __half2(
            __float2half_rn(v10 - __half2float(h10)),
            __float2half_rn(v11 - __half2float(h11)));
    }
}

// ---------------------------------------------------------------------------
// Launch
// ---------------------------------------------------------------------------
extern "C" void kernel_launch(void* const* d_in, const int* in_sizes, int n_in,
                              void* d_out, int out_size)
{
    const float* x      = (const float*)d_in[0];
    const float* w_attn = (const float*)d_in[1];
    const float* b_attn = (const float*)d_in[2];
    const float* w_proj = (const float*)d_in[3];
    const float* b_proj = (const float*)d_in[4];
    float* out = (float*)d_out;

    float *gq, *gk;
    __half *gvp, *xhi, *xlo, *wah, *wph, *yhi, *ylo;
    cudaGetSymbolAddress((void**)&gq,  g_q);
    cudaGetSymbolAddress((void**)&gk,  g_k);
    cudaGetSymbolAddress((void**)&gvp, g_vp);
    cudaGetSymbolAddress((void**)&xhi, g_xhi);
    cudaGetSymbolAddress((void**)&xlo, g_xlo);
    cudaGetSymbolAddress((void**)&wah, g_wah);
    cudaGetSymbolAddress((void**)&wph, g_wph);
    cudaGetSymbolAddress((void**)&yhi, g_yhi);
    cudaGetSymbolAddress((void**)&ylo, g_ylo);

    cudaFuncSetAttribute(hgemm_2p,  cudaFuncAttributeMaxDynamicSharedMemorySize, GEMM_SMEM);
    cudaFuncSetAttribute(hgemm_qkv, cudaFuncAttributeMaxDynamicSharedMemorySize, GEMM_SMEM);
    cudaFuncSetAttribute(attn_tc,   cudaFuncAttributeMaxDynamicSharedMemorySize, AT_SMEM);

    // 0) split x (hi/lo fp16); convert weights to fp16
    {
        int n4;
        n4 = (Mrows * Cn) / 4;
        split2h<<<(n4 + 255) / 256, 256>>>(x, xhi, xlo, n4);
        n4 = (Cn * QKV_N) / 4;
        conv_h<<<(n4 + 255) / 256, 256>>>(w_attn, wah, n4);
        n4 = (Cn * Cn) / 4;
        conv_h<<<(n4 + 255) / 256, 256>>>(w_proj, wph, n4);
    }
    // 1) QKV projection -> head-contiguous pre-converted Q/K/V
    {
        dim3 grid(QKV_N / GBN, Mrows / GBM);
        hgemm_qkv<<<grid, 256, GEMM_SMEM>>>(xhi, xlo, wah, b_attn,
                                            gq, gk, gvp, Mrows, QKV_N, Cn);
    }
    // 2) Causal attention (pure-cp.async staging, zero conversions)
    {
        dim3 grid(Tn / AT_BQ, Hn, Bn);
        attn_tc<<<grid, 256, AT_SMEM>>>(gq, gk, gvp, yhi, ylo);
    }
    // 3) Output projection
    {
        dim3 grid(Cn / GBN, Mrows / GBM);
        hgemm_2p<<<grid, 256, GEMM_SMEM>>>(yhi, ylo, wph, b_proj,
                                           out, Mrows, Cn, Cn);
    }
}

// round 16
// speedup vs baseline: 1.5288x; 1.0867x over previous
#include <cuda_runtime.h>
#include <cuda_bf16.h>
#include <cuda_fp16.h>
#include <math.h>
#include <stdint.h>

// Problem constants
#define Bn  2
#define Tn  2048
#define Cn  1024
#define Hn  16
#define HDn 64
#define QKV_N (3*Cn)          // 3072
#define Mrows (Bn*Tn)         // 4096
#define SCALE 0.125f

// Scratch (allocation-free: __device__ globals)
__device__ __half g_q [(size_t)Bn * Hn * Tn * HDn];         // fp16(q*scale), head-contig
__device__ __half g_k [(size_t)Bn * Hn * Tn * HDn];         // fp16(k), head-contig
__device__ __half g_vp[(size_t)Bn * Hn * (Tn/2) * 2 * HDn]; // fp16 V pair-packed
__device__ __half g_xhi[(size_t)Mrows * Cn];
__device__ __half g_xlo[(size_t)Mrows * Cn];
__device__ __half g_wah[(size_t)Cn * QKV_N];
__device__ __half g_wph[(size_t)Cn * Cn];
__device__ __half g_yhi[(size_t)Mrows * Cn];
__device__ __half g_ylo[(size_t)Mrows * Cn];

// ===========================================================================
// helpers
// ===========================================================================
__device__ __forceinline__ void cpasync16(uint32_t dst, const void* src) {
    asm volatile("cp.async.cg.shared.global [%0], [%1], 16;" :: "r"(dst), "l"(src));
}
__device__ __forceinline__ void ldsm4(uint32_t r[4], uint32_t addr) {
    asm volatile("ldmatrix.sync.aligned.m8n8.x4.shared.b16 {%0,%1,%2,%3}, [%4];"
                 : "=r"(r[0]), "=r"(r[1]), "=r"(r[2]), "=r"(r[3]) : "r"(addr));
}
__device__ __forceinline__ void ldsm4t(uint32_t r[4], uint32_t addr) {
    asm volatile("ldmatrix.sync.aligned.m8n8.x4.trans.shared.b16 {%0,%1,%2,%3}, [%4];"
                 : "=r"(r[0]), "=r"(r[1]), "=r"(r[2]), "=r"(r[3]) : "r"(addr));
}
__device__ __forceinline__ void mma_f16(float d[4], const uint32_t a[4],
                                        uint32_t b0, uint32_t b1) {
    asm volatile(
        "mma.sync.aligned.m16n8k16.row.col.f32.f16.f16.f32 "
        "{%0,%1,%2,%3}, {%4,%5,%6,%7}, {%8,%9}, {%0,%1,%2,%3};"
        : "+f"(d[0]), "+f"(d[1]), "+f"(d[2]), "+f"(d[3])
        : "r"(a[0]), "r"(a[1]), "r"(a[2]), "r"(a[3]), "r"(b0), "r"(b1));
}

// ===========================================================================
// fp32 -> fp16 hi/lo split  and  fp32 -> fp16 convert (weights)
// ===========================================================================
__global__ __launch_bounds__(256)
void split2h(const float* __restrict__ src, __half* __restrict__ hi,
             __half* __restrict__ lo, int n4)
{
    int i = blockIdx.x * blockDim.x + threadIdx.x;
    if (i >= n4) return;
    float4 v = ((const float4*)src)[i];
    __half hx = __float2half_rn(v.x), hy = __float2half_rn(v.y);
    __half hz = __float2half_rn(v.z), hw = __float2half_rn(v.w);
    ((__half2*)hi)[2 * i]     = __half2(hx, hy);
    ((__half2*)hi)[2 * i + 1] = __half2(hz, hw);
    ((__half2*)lo)[2 * i] = __half2(
        __float2half_rn(v.x - __half2float(hx)),
        __float2half_rn(v.y - __half2float(hy)));
    ((__half2*)lo)[2 * i + 1] = __half2(
        __float2half_rn(v.z - __half2float(hz)),
        __float2half_rn(v.w - __half2float(hw)));
}

__global__ __launch_bounds__(256)
void conv_h(const float* __restrict__ src, __half* __restrict__ dst, int n4)
{
    int i = blockIdx.x * blockDim.x + threadIdx.x;
    if (i >= n4) return;
    float4 v = ((const float4*)src)[i];
    ((__half2*)dst)[2 * i]     = __floats2half2_rn(v.x, v.y);
    ((__half2*)dst)[2 * i + 1] = __floats2half2_rn(v.z, v.w);
}

// ===========================================================================
// GEMM mainloop shared macros (fp16 2-pass, R10 winner structure)
// ===========================================================================
#define GBM 128
#define GBN 128
#define GBK 32
#define ASTR 40
#define BSTR 136
#define OFF_AHI 0
#define OFF_ALO 10240
#define OFF_BHI 20480
#define STAGE_BYTES 29184
#define GEMM_SMEM (2*STAGE_BYTES)

#define GEMM_PROLOGUE()                                                      \
    extern __shared__ char gsm[];                                            \
    const int tid  = threadIdx.x;                                            \
    const int warp = tid >> 5;                                               \
    const int lane = tid & 31;                                               \
    const int g  = lane >> 2;                                                \
    const int tg = lane & 3;                                                 \
    const int bm = blockIdx.y * GBM;                                         \
    const int bn = blockIdx.x * GBN;                                         \
    const int warp_m = (warp >> 1) * 32;                                     \
    const int warp_n = (warp & 1) * 64;                                      \
    const int ar = tid >> 2, ac = (tid & 3) * 8;                             \
    const int br = tid >> 4, bc = (tid & 15) * 8;                            \
    const __half* aih = Ahi_g + (size_t)(bm + ar) * K + ac;                  \
    const __half* ail = Alo_g + (size_t)(bm + ar) * K + ac;                  \
    const __half* bhg = Bh_g  + (size_t)br * N + bn + bc;                    \
    const size_t a64 = (size_t)64 * K;                                       \
    const size_t b16 = (size_t)16 * N;                                       \
    const uint32_t smb = (uint32_t)__cvta_generic_to_shared(gsm);            \
    const uint32_t dA  = (uint32_t)(ar * ASTR + ac) * 2;                     \
    const uint32_t dA2 = (uint32_t)((ar + 64) * ASTR + ac) * 2;              \
    const uint32_t dB  = (uint32_t)(br * BSTR + bc) * 2;                     \
    const uint32_t dB2 = (uint32_t)((br + 16) * BSTR + bc) * 2;              \
    float acc[2][8][4];                                                      \
    _Pragma("unroll")                                                        \
    for (int mt = 0; mt < 2; mt++)                                           \
        _Pragma("unroll")                                                    \
        for (int nt = 0; nt < 8; nt++)                                       \
            _Pragma("unroll")                                                \
            for (int i = 0; i < 4; i++) acc[mt][nt][i] = 0.f;                \
    const int NK = K / GBK;

#define ISSUE_STAGE(s, kit) do {                                             \
    uint32_t so = smb + (uint32_t)(s) * STAGE_BYTES;                         \
    size_t ka = (size_t)(kit) * GBK;                                         \
    size_t kb = (size_t)(kit) * GBK * (size_t)N;                             \
    cpasync16(so + OFF_AHI + dA,  aih + ka);                                 \
    cpasync16(so + OFF_AHI + dA2, aih + a64 + ka);                           \
    cpasync16(so + OFF_ALO + dA,  ail + ka);                                 \
    cpasync16(so + OFF_ALO + dA2, ail + a64 + ka);                           \
    cpasync16(so + OFF_BHI + dB,  bhg + kb);                                 \
    cpasync16(so + OFF_BHI + dB2, bhg + b16 + kb);                           \
    asm volatile("cp.async.commit_group;");                                  \
} while (0)

#define GEMM_MAINLOOP()                                                      \
    ISSUE_STAGE(0, 0);                                                       \
    const int a_r = lane & 15;                                               \
    const int a_c = (lane >> 4) * 8;                                         \
    for (int it = 0; it < NK; it++) {                                        \
        if (it + 1 < NK) {                                                   \
            ISSUE_STAGE((it + 1) & 1, it + 1);                               \
            asm volatile("cp.async.wait_group 1;");                          \
        } else {                                                             \
            asm volatile("cp.async.wait_group 0;");                          \
        }                                                                    \
        __syncthreads();                                                     \
        const uint32_t sb = smb + (uint32_t)(it & 1) * STAGE_BYTES;          \
        _Pragma("unroll")                                                    \
        for (int ks = 0; ks < 2; ks++) {                                     \
            const int kk = ks * 16;                                          \
            uint32_t ah[2][4], al[2][4];                                     \
            _Pragma("unroll")                                                \
            for (int mt = 0; mt < 2; mt++) {                                 \
                uint32_t off = (uint32_t)((warp_m + mt * 16 + a_r) * ASTR    \
                                          + kk + a_c) * 2;                   \
                ldsm4(ah[mt], sb + OFF_AHI + off);                           \
                ldsm4(al[mt], sb + OFF_ALO + off);                           \
            }                                                                \
            _Pragma("unroll")                                                \
            for (int np = 0; np < 4; np++) {                                 \
                uint32_t bh[4];                                              \
                uint32_t off = (uint32_t)((kk + a_r) * BSTR + warp_n         \
                                          + np * 16 + a_c) * 2;              \
                ldsm4t(bh, sb + OFF_BHI + off);                              \
                _Pragma("unroll")                                            \
                for (int pass = 0; pass < 2; pass++) {                       \
                    _Pragma("unroll")                                        \
                    for (int half = 0; half < 2; half++) {                   \
                        const int nt = np * 2 + half;                        \
                        _Pragma("unroll")                                    \
                        for (int mt = 0; mt < 2; mt++) {                     \
                            mma_f16(acc[mt][nt], pass ? al[mt] : ah[mt],     \
                                    bh[half * 2], bh[half * 2 + 1]);         \
                        }                                                    \
                    }                                                        \
                }                                                            \
            }                                                                \
        }                                                                    \
        __syncthreads();                                                     \
    }

// ---------------------------------------------------------------------------
// Generic GEMM (used for proj): C fp32 row-major + bias
// ---------------------------------------------------------------------------
__global__ __launch_bounds__(256, 2)
void hgemm_2p(const __half* __restrict__ Ahi_g, const __half* __restrict__ Alo_g,
              const __half* __restrict__ Bh_g,
              const float* __restrict__ bias, float* __restrict__ C,
              int M, int N, int K)
{
    GEMM_PROLOGUE();
    GEMM_MAINLOOP();
    #pragma unroll
    for (int nt = 0; nt < 8; nt++) {
        const int col = bn + warp_n + nt * 8 + 2 * tg;
        const float2 bs = *(const float2*)&bias[col];
        #pragma unroll
        for (int mt = 0; mt < 2; mt++) {
            const int row0 = bm + warp_m + mt * 16 + g;
            float2 o0 = make_float2(acc[mt][nt][0] + bs.x, acc[mt][nt][1] + bs.y);
            float2 o1 = make_float2(acc[mt][nt][2] + bs.x, acc[mt][nt][3] + bs.y);
            *(float2*)&C[(size_t)row0 * N + col]       = o0;
            *(float2*)&C[(size_t)(row0 + 8) * N + col] = o1;
        }
    }
}

// ---------------------------------------------------------------------------
// QKV GEMM: head-contiguous fp16 Q(scaled)/K, fp16 pair-packed V.
// ---------------------------------------------------------------------------
__global__ __launch_bounds__(256, 2)
void hgemm_qkv(const __half* __restrict__ Ahi_g, const __half* __restrict__ Alo_g,
               const __half* __restrict__ Bh_g,
               const float* __restrict__ bias,
               __half* __restrict__ Q, __half* __restrict__ Kd,
               __half* __restrict__ Vp,
               int M, int N, int K)
{
    GEMM_PROLOGUE();
    GEMM_MAINLOOP();
    #pragma unroll
    for (int nt = 0; nt < 8; nt++) {
        const int col = bn + warp_n + nt * 8 + 2 * tg;      // col, col+1 (even)
        const float2 bs = *(const float2*)&bias[col];
        const int sec = col >> 10;            // 0=Q 1=K 2=V
        const int hh  = (col & 1023) >> 6;
        const int dd  = col & 63;
        #pragma unroll
        for (int mt = 0; mt < 2; mt++) {
            const int r0 = bm + warp_m + mt * 16 + g;
            #pragma unroll
            for (int rr = 0; rr < 2; rr++) {
                const int row = r0 + rr * 8;
                const int bb = row >> 11;
                const int tt = row & 2047;
                float v0 = acc[mt][nt][2 * rr]     + bs.x;
                float v1 = acc[mt][nt][2 * rr + 1] + bs.y;
                if (sec == 0) {
                    __half* p = Q + (((size_t)(bb * Hn + hh) * Tn + tt) << 6) + dd;
                    *(__half2*)p = __floats2half2_rn(v0 * SCALE, v1 * SCALE);
                } else if (sec == 1) {
                    __half* p = Kd + (((size_t)(bb * Hn + hh) * Tn + tt) << 6) + dd;
                    *(__half2*)p = __floats2half2_rn(v0, v1);
                } else {
                    __half* p = Vp + (((size_t)(bb * Hn + hh) * (Tn / 2)
                                       + (tt >> 1)) << 7) + (tt & 1);
                    p[dd * 2]       = __float2half_rn(v0);
                    p[(dd + 1) * 2] = __float2half_rn(v1);
                }
            }
        }
    }
}

// ===========================================================================
// Flash attention v6: all-fp16 operands, pre-converted by QKV epilogue.
// Q: direct gmem A-frags. K, V: pure cp.async, triple buffer, 1 sync/tile.
// QK fp16 m16n8k16 (32 MMAs/tile), PV fp16 2-pass (64 MMAs/tile).
// ===========================================================================
#define AT_BQ   128
#define AT_BKV  64
#define KHW     36                 // K row stride, uint32 words (72 halves)
#define VSTR    72                 // V pair-row stride, uint32 words
#define KBUF_W  (AT_BKV * KHW)     // 2304 words
#define VBUF_W  (32 * VSTR)        // 2304 words
#define AT_SMEM ((3 * KBUF_W + 3 * VBUF_W) * 4)   // 55296 bytes

__global__ __launch_bounds__(256)
void attn_tc(const __half* __restrict__ gq, const __half* __restrict__ gk,
             const __half* __restrict__ gvp,
             __half* __restrict__ yhi, __half* __restrict__ ylo)
{
    extern __shared__ uint32_t apool[];   // [K0|K1|K2|V0|V1|V2]

    const int b = blockIdx.z, h = blockIdx.y;
    const int qtile = gridDim.x - 1 - blockIdx.x;   // heavy tiles first
    const int q0 = qtile * AT_BQ;
    const int tid  = threadIdx.x;
    const int warp = tid >> 5;
    const int lane = tid & 31;
    const int g  = lane >> 2;
    const int tg = lane & 3;

    const __half* kbp = gk  + ((size_t)(b * Hn + h) * Tn) * HDn;
    const __half* vbp = gvp + ((size_t)(b * Hn + h) * (Tn / 2)) * 2 * HDn;

    // ---- Q A-frags straight from head-contiguous fp16 gmem ----
    uint32_t Aq[4][4];
    {
        const uint32_t* qw = (const uint32_t*)(gq + ((size_t)(b * Hn + h) * Tn) * HDn);
        const int r0 = q0 + warp * 16 + g;
        #pragma unroll
        for (int kk = 0; kk < 4; kk++) {
            Aq[kk][0] = qw[(size_t)r0 * 32 + kk * 8 + tg];
            Aq[kk][1] = qw[(size_t)(r0 + 8) * 32 + kk * 8 + tg];
            Aq[kk][2] = qw[(size_t)r0 * 32 + kk * 8 + tg + 4];
            Aq[kk][3] = qw[(size_t)(r0 + 8) * 32 + kk * 8 + tg + 4];
        }
    }

    // cp.async geometry: K rows 64x128B -> 2 granules/thread; V same
    const uint32_t smb = (uint32_t)__cvta_generic_to_shared(apool);
    int krow[2], kcol[2]; uint32_t kdst[2];
    int vrow[2], vcol[2]; uint32_t vdst[2];
    #pragma unroll
    for (int i = 0; i < 2; i++) {
        int f = i * 256 + tid;            // 0..511
        krow[i] = f >> 3;                 // 0..63
        kcol[i] = (f & 7) * 8;            // half offset
        kdst[i] = (uint32_t)(krow[i] * KHW + (f & 7) * 4) * 4;
        vrow[i] = f >> 4;                 // pair 0..31
        vcol[i] = (f & 15) * 8;           // half offset
        vdst[i] = (uint32_t)(vrow[i] * VSTR + (f & 15) * 4) * 4;
    }

    const int NT = (q0 + AT_BQ) / AT_BKV;

    #define AT_ISSUE(tile, s) do {                                            \
        const uint32_t _ks = smb + (uint32_t)(s) * (KBUF_W * 4);              \
        const uint32_t _vs = smb + (uint32_t)(3 * KBUF_W + (s) * VBUF_W) * 4; \
        const int _kt = (tile) * AT_BKV;                                      \
        _Pragma("unroll")                                                     \
        for (int _i = 0; _i < 2; _i++) {                                      \
            cpasync16(_ks + kdst[_i],                                         \
                      kbp + (size_t)(_kt + krow[_i]) * HDn + kcol[_i]);       \
            cpasync16(_vs + vdst[_i],                                         \
                      vbp + (size_t)(_kt / 2 + vrow[_i]) * 2 * HDn + vcol[_i]);\
        }                                                                     \
        asm volatile("cp.async.commit_group;");                               \
    } while (0)

    AT_ISSUE(0, 0);
    if (NT > 1) AT_ISSUE(1, 1);

    float O[8][4];
    #pragma unroll
    for (int nt = 0; nt < 8; nt++)
        #pragma unroll
        for (int i = 0; i < 4; i++) O[nt][i] = 0.f;

    float m0 = -INFINITY, m1 = -INFINITY;
    float l0 = 0.f, l1 = 0.f;

    const int qi0 = q0 + warp * 16 + g;
    const int qi1 = qi0 + 8;
    const int w_qmax = q0 + warp * 16 + 15;
    const int w_qmin = q0 + warp * 16;

    for (int t = 0; t < NT; t++) {
        if (t + 1 < NT) asm volatile("cp.async.wait_group 1;");
        else            asm volatile("cp.async.wait_group 0;");
        __syncthreads();
        if (t + 2 < NT) AT_ISSUE(t + 2, (t + 2) % 3);

        const int kt = t * AT_BKV;
        const uint32_t* Kw = apool + (t % 3) * KBUF_W;
        const uint32_t* Vp = apool + 3 * KBUF_W + (t % 3) * VBUF_W;

        if (kt <= w_qmax) {
            // ---- S = Q @ K^T (fp16 m16n8k16, 32 MMAs) ----
            float S[8][4];
            #pragma unroll
            for (int nt = 0; nt < 8; nt++) {
                S[nt][0] = S[nt][1] = S[nt][2] = S[nt][3] = 0.f;
            }
            #pragma unroll
            for (int kk = 0; kk < 4; kk++) {
                #pragma unroll
                for (int nt = 0; nt < 8; nt++) {
                    const int rw = (nt * 8 + g) * KHW + kk * 8 + tg;
                    mma_f16(S[nt], Aq[kk], Kw[rw], Kw[rw + 4]);
                }
            }

            const bool need_mask = (kt + AT_BKV - 1 > w_qmin);
            if (need_mask) {
                #pragma unroll
                for (int nt = 0; nt < 8; nt++) {
                    int j0 = kt + nt * 8 + 2 * tg;
                    int j1 = j0 + 1;
                    if (j0 > qi0) S[nt][0] = -INFINITY;
                    if (j1 > qi0) S[nt][1] = -INFINITY;
                    if (j0 > qi1) S[nt][2] = -INFINITY;
                    if (j1 > qi1) S[nt][3] = -INFINITY;
                }
            }

            // ---- online softmax ----
            float mc0 = -INFINITY, mc1 = -INFINITY;
            #pragma unroll
            for (int nt = 0; nt < 8; nt++) {
                mc0 = fmaxf(mc0, fmaxf(S[nt][0], S[nt][1]));
                mc1 = fmaxf(mc1, fmaxf(S[nt][2], S[nt][3]));
            }
            mc0 = fmaxf(mc0, __shfl_xor_sync(0xffffffffu, mc0, 1));
            mc0 = fmaxf(mc0, __shfl_xor_sync(0xffffffffu, mc0, 2));
            mc1 = fmaxf(mc1, __shfl_xor_sync(0xffffffffu, mc1, 1));
            mc1 = fmaxf(mc1, __shfl_xor_sync(0xffffffffu, mc1, 2));

            float mn0 = fmaxf(m0, mc0);
            float mn1 = fmaxf(m1, mc1);
            float corr0 = __expf(m0 - mn0);
            float corr1 = __expf(m1 - mn1);
            m0 = mn0; m1 = mn1;

            float ps0 = 0.f, ps1 = 0.f;
            #pragma unroll
            for (int nt = 0; nt < 8; nt++) {
                S[nt][0] = __expf(S[nt][0] - mn0);
                S[nt][1] = __expf(S[nt][1] - mn0);
                S[nt][2] = __expf(S[nt][2] - mn1);
                S[nt][3] = __expf(S[nt][3] - mn1);
                ps0 += S[nt][0] + S[nt][1];
                ps1 += S[nt][2] + S[nt][3];
            }
            ps0 += __shfl_xor_sync(0xffffffffu, ps0, 1);
            ps0 += __shfl_xor_sync(0xffffffffu, ps0, 2);
            ps1 += __shfl_xor_sync(0xffffffffu, ps1, 1);
            ps1 += __shfl_xor_sync(0xffffffffu, ps1, 2);
            l0 = l0 * corr0 + ps0;
            l1 = l1 * corr1 + ps1;

            #pragma unroll
            for (int nt = 0; nt < 8; nt++) {
                O[nt][0] *= corr0; O[nt][1] *= corr0;
                O[nt][2] *= corr1; O[nt][3] *= corr1;
            }

            // ---- O += P @ V, fp16 2-pass (P hi/lo exact, V fp16) ----
            #pragma unroll
            for (int s = 0; s < 4; s++) {
                uint32_t aph[4], apl[4];
                const float pv[8] = {
                    S[2*s  ][0], S[2*s  ][1], S[2*s  ][2], S[2*s  ][3],
                    S[2*s+1][0], S[2*s+1][1], S[2*s+1][2], S[2*s+1][3]
                };
                #pragma unroll
                for (int q = 0; q < 4; q++) {
                    __half2 hp = __floats2half2_rn(pv[2*q], pv[2*q+1]);
                    aph[q] = *(uint32_t*)&hp;
                    float2 hf = __half22float2(hp);
                    __half2 lp = __floats2half2_rn(pv[2*q] - hf.x, pv[2*q+1] - hf.y);
                    apl[q] = *(uint32_t*)&lp;
                }
                const int pr0 = (8 * s + tg) * VSTR;
                const int pr1 = (8 * s + tg + 4) * VSTR;
                #pragma unroll
                for (int dd = 0; dd < 8; dd++) {
                    const int dc = dd * 8 + g;
                    uint32_t b0 = Vp[pr0 + dc];
                    uint32_t b1 = Vp[pr1 + dc];
                    mma_f16(O[dd], aph, b0, b1);
                    mma_f16(O[dd], apl, b0, b1);
                }
            }
        }
    }
    #undef AT_ISSUE

    // ---- finalize: divide by l, split to fp16 hi/lo, store ----
    const float inv0 = 1.f / l0;
    const float inv1 = 1.f / l1;
    const size_t row0 = (size_t)(b * Tn + qi0) * Cn + h * HDn;
    const size_t row1 = (size_t)(b * Tn + qi1) * Cn + h * HDn;
    #pragma unroll
    for (int nt = 0; nt < 8; nt++) {
        int c = nt * 8 + 2 * tg;
        float v00 = O[nt][0] * inv0, v01 = O[nt][1] * inv0;
        float v10 = O[nt][2] * inv1, v11 = O[nt][3] * inv1;
        __half h00 = __float2half_rn(v00), h01 = __float2half_rn(v01);
        __half h10 = __float2half_rn(v10), h11 = __float2half_rn(v11);
        *(__half2*)&yhi[row0 + c] = __half2(h00, h01);
        *(__half2*)&yhi[row1 + c] = __half2(h10, h11);
        *(__half2*)&ylo[row0 + c] = __half2(
            __float2half_rn(v00 - __half2float(h00)),
            __float2half_rn(v01 - __half2float(h01)));
        *(__half2*)&ylo[row1 + c] = __half2(
            __float2half_rn(v10 - __half2float(h10)),
            __float2half_rn(v11 - __half2float(h11)));
    }
}

// ---------------------------------------------------------------------------
// Launch
// ---------------------------------------------------------------------------
extern "C" void kernel_launch(void* const* d_in, const int* in_sizes, int n_in,
                              void* d_out, int out_size)
{
    const float* x      = (const float*)d_in[0];
    const float* w_attn = (const float*)d_in[1];
    const float* b_attn = (const float*)d_in[2];
    const float* w_proj = (const float*)d_in[3];
    const float* b_proj = (const float*)d_in[4];
    float* out = (float*)d_out;

    __half *gq, *gk, *gvp, *xhi, *xlo, *wah, *wph, *yhi, *ylo;
    cudaGetSymbolAddress((void**)&gq,  g_q);
    cudaGetSymbolAddress((void**)&gk,  g_k);
    cudaGetSymbolAddress((void**)&gvp, g_vp);
    cudaGetSymbolAddress((void**)&xhi, g_xhi);
    cudaGetSymbolAddress((void**)&xlo, g_xlo);
    cudaGetSymbolAddress((void**)&wah, g_wah);
    cudaGetSymbolAddress((void**)&wph, g_wph);
    cudaGetSymbolAddress((void**)&yhi, g_yhi);
    cudaGetSymbolAddress((void**)&ylo, g_ylo);

    cudaFuncSetAttribute(hgemm_2p,  cudaFuncAttributeMaxDynamicSharedMemorySize, GEMM_SMEM);
    cudaFuncSetAttribute(hgemm_qkv, cudaFuncAttributeMaxDynamicSharedMemorySize, GEMM_SMEM);
    cudaFuncSetAttribute(attn_tc,   cudaFuncAttributeMaxDynamicSharedMemorySize, AT_SMEM);

    // 0) split x (hi/lo fp16); convert weights to fp16
    {
        int n4;
        n4 = (Mrows * Cn) / 4;
        split2h<<<(n4 + 255) / 256, 256>>>(x, xhi, xlo, n4);
        n4 = (Cn * QKV_N) / 4;
        conv_h<<<(n4 + 255) / 256, 256>>>(w_attn, wah, n4);
        n4 = (Cn * Cn) / 4;
        conv_h<<<(n4 + 255) / 256, 256>>>(w_proj, wph, n4);
    }
    // 1) QKV projection -> head-contiguous fp16 Q/K + pair-packed V
    {
        dim3 grid(QKV_N / GBN, Mrows / GBM);
        hgemm_qkv<<<grid, 256, GEMM_SMEM>>>(xhi, xlo, wah, b_attn,
                                            gq, gk, gvp, Mrows, QKV_N, Cn);
    }
    // 2) Causal attention (all-fp16 operands, pure cp.async staging)
    {
        dim3 grid(Tn / AT_BQ, Hn, Bn);
        attn_tc<<<grid, 256, AT_SMEM>>>(gq, gk, gvp, yhi, ylo);
    }
    // 3) Output projection
    {
        dim3 grid(Cn / GBN, Mrows / GBM);
        hgemm_2p<<<grid, 256, GEMM_SMEM>>>(yhi, ylo, wph, b_proj,
                                           out, Mrows, Cn, Cn);
    }
}

// round 17
// speedup vs baseline: 1.8754x; 1.2267x over previous
#include <cuda_runtime.h>
#include <cuda_bf16.h>
#include <cuda_fp16.h>
#include <math.h>
#include <stdint.h>

// Problem constants
#define Bn  2
#define Tn  2048
#define Cn  1024
#define Hn  16
#define HDn 64
#define QKV_N (3*Cn)          // 3072
#define Mrows (Bn*Tn)         // 4096
#define SCALE 0.125f

// Scratch (allocation-free: __device__ globals)
__device__ __half g_q [(size_t)Bn * Hn * Tn * HDn];         // fp16(q*scale), head-contig
__device__ __half g_k [(size_t)Bn * Hn * Tn * HDn];         // fp16(k), head-contig
__device__ __half g_vp[(size_t)Bn * Hn * (Tn/2) * 2 * HDn]; // fp16 V pair-packed
__device__ __half g_xh [(size_t)Mrows * Cn];                // fp16(x), unsplit
__device__ __half g_wah[(size_t)Cn * QKV_N];
__device__ __half g_wph[(size_t)Cn * Cn];
__device__ __half g_yhi[(size_t)Mrows * Cn];
__device__ __half g_ylo[(size_t)Mrows * Cn];

// ===========================================================================
// helpers
// ===========================================================================
__device__ __forceinline__ void cpasync16(uint32_t dst, const void* src) {
    asm volatile("cp.async.cg.shared.global [%0], [%1], 16;" :: "r"(dst), "l"(src));
}
__device__ __forceinline__ void ldsm4(uint32_t r[4], uint32_t addr) {
    asm volatile("ldmatrix.sync.aligned.m8n8.x4.shared.b16 {%0,%1,%2,%3}, [%4];"
                 : "=r"(r[0]), "=r"(r[1]), "=r"(r[2]), "=r"(r[3]) : "r"(addr));
}
__device__ __forceinline__ void ldsm4t(uint32_t r[4], uint32_t addr) {
    asm volatile("ldmatrix.sync.aligned.m8n8.x4.trans.shared.b16 {%0,%1,%2,%3}, [%4];"
                 : "=r"(r[0]), "=r"(r[1]), "=r"(r[2]), "=r"(r[3]) : "r"(addr));
}
__device__ __forceinline__ void mma_f16(float d[4], const uint32_t a[4],
                                        uint32_t b0, uint32_t b1) {
    asm volatile(
        "mma.sync.aligned.m16n8k16.row.col.f32.f16.f16.f32 "
        "{%0,%1,%2,%3}, {%4,%5,%6,%7}, {%8,%9}, {%0,%1,%2,%3};"
        : "+f"(d[0]), "+f"(d[1]), "+f"(d[2]), "+f"(d[3])
        : "r"(a[0]), "r"(a[1]), "r"(a[2]), "r"(a[3]), "r"(b0), "r"(b1));
}

// ===========================================================================
// fp32 -> fp16 hi/lo split  and  fp32 -> fp16 convert
// ===========================================================================
__global__ __launch_bounds__(256)
void conv_h(const float* __restrict__ src, __half* __restrict__ dst, int n4)
{
    int i = blockIdx.x * blockDim.x + threadIdx.x;
    if (i >= n4) return;
    float4 v = ((const float4*)src)[i];
    ((__half2*)dst)[2 * i]     = __floats2half2_rn(v.x, v.y);
    ((__half2*)dst)[2 * i + 1] = __floats2half2_rn(v.z, v.w);
}

// ===========================================================================
// 2-pass GEMM (proj): C = (Ahi+Alo)@Bh + bias   (R10 winner structure)
// ===========================================================================
#define GBM 128
#define GBN 128
#define GBK 32
#define ASTR 40
#define BSTR 136
#define OFF_AHI 0
#define OFF_ALO 10240
#define OFF_BHI 20480
#define STAGE_BYTES 29184
#define GEMM_SMEM (2*STAGE_BYTES)

__global__ __launch_bounds__(256, 2)
void hgemm_2p(const __half* __restrict__ Ahi_g, const __half* __restrict__ Alo_g,
              const __half* __restrict__ Bh_g,
              const float* __restrict__ bias, float* __restrict__ C,
              int M, int N, int K)
{
    extern __shared__ char gsm[];
    const int tid  = threadIdx.x;
    const int warp = tid >> 5;
    const int lane = tid & 31;
    const int g  = lane >> 2;
    const int tg = lane & 3;

    const int bm = blockIdx.y * GBM;
    const int bn = blockIdx.x * GBN;
    const int warp_m = (warp >> 1) * 32;
    const int warp_n = (warp & 1) * 64;

    const int ar = tid >> 2, ac = (tid & 3) * 8;
    const int br = tid >> 4, bc = (tid & 15) * 8;
    const __half* aih = Ahi_g + (size_t)(bm + ar) * K + ac;
    const __half* ail = Alo_g + (size_t)(bm + ar) * K + ac;
    const __half* bhg = Bh_g  + (size_t)br * N + bn + bc;
    const size_t a64 = (size_t)64 * K;
    const size_t b16 = (size_t)16 * N;

    const uint32_t smb = (uint32_t)__cvta_generic_to_shared(gsm);
    const uint32_t dA  = (uint32_t)(ar * ASTR + ac) * 2;
    const uint32_t dA2 = (uint32_t)((ar + 64) * ASTR + ac) * 2;
    const uint32_t dB  = (uint32_t)(br * BSTR + bc) * 2;
    const uint32_t dB2 = (uint32_t)((br + 16) * BSTR + bc) * 2;

    float acc[2][8][4];
    #pragma unroll
    for (int mt = 0; mt < 2; mt++)
        #pragma unroll
        for (int nt = 0; nt < 8; nt++)
            #pragma unroll
            for (int i = 0; i < 4; i++) acc[mt][nt][i] = 0.f;

    const int NK = K / GBK;

    #define ISSUE_STAGE(s, kit) do {                                         \
        uint32_t so = smb + (uint32_t)(s) * STAGE_BYTES;                     \
        size_t ka = (size_t)(kit) * GBK;                                     \
        size_t kb = (size_t)(kit) * GBK * (size_t)N;                         \
        cpasync16(so + OFF_AHI + dA,  aih + ka);                             \
        cpasync16(so + OFF_AHI + dA2, aih + a64 + ka);                       \
        cpasync16(so + OFF_ALO + dA,  ail + ka);                             \
        cpasync16(so + OFF_ALO + dA2, ail + a64 + ka);                       \
        cpasync16(so + OFF_BHI + dB,  bhg + kb);                             \
        cpasync16(so + OFF_BHI + dB2, bhg + b16 + kb);                       \
        asm volatile("cp.async.commit_group;");                              \
    } while (0)

    ISSUE_STAGE(0, 0);

    const int a_r = lane & 15;
    const int a_c = (lane >> 4) * 8;

    for (int it = 0; it < NK; it++) {
        if (it + 1 < NK) {
            ISSUE_STAGE((it + 1) & 1, it + 1);
            asm volatile("cp.async.wait_group 1;");
        } else {
            asm volatile("cp.async.wait_group 0;");
        }
        __syncthreads();

        const uint32_t sb = smb + (uint32_t)(it & 1) * STAGE_BYTES;
        #pragma unroll
        for (int ks = 0; ks < 2; ks++) {
            const int kk = ks * 16;
            uint32_t ah[2][4], al[2][4];
            #pragma unroll
            for (int mt = 0; mt < 2; mt++) {
                uint32_t off = (uint32_t)((warp_m + mt * 16 + a_r) * ASTR + kk + a_c) * 2;
                ldsm4(ah[mt], sb + OFF_AHI + off);
                ldsm4(al[mt], sb + OFF_ALO + off);
            }
            #pragma unroll
            for (int np = 0; np < 4; np++) {
                uint32_t bh[4];
                uint32_t off = (uint32_t)((kk + a_r) * BSTR + warp_n + np * 16 + a_c) * 2;
                ldsm4t(bh, sb + OFF_BHI + off);
                #pragma unroll
                for (int pass = 0; pass < 2; pass++) {
                    #pragma unroll
                    for (int half = 0; half < 2; half++) {
                        const int nt = np * 2 + half;
                        #pragma unroll
                        for (int mt = 0; mt < 2; mt++) {
                            mma_f16(acc[mt][nt], pass ? al[mt] : ah[mt],
                                    bh[half * 2], bh[half * 2 + 1]);
                        }
                    }
                }
            }
        }
        __syncthreads();
    }
    #undef ISSUE_STAGE

    #pragma unroll
    for (int nt = 0; nt < 8; nt++) {
        const int col = bn + warp_n + nt * 8 + 2 * tg;
        const float2 bs = *(const float2*)&bias[col];
        #pragma unroll
        for (int mt = 0; mt < 2; mt++) {
            const int row0 = bm + warp_m + mt * 16 + g;
            float2 o0 = make_float2(acc[mt][nt][0] + bs.x, acc[mt][nt][1] + bs.y);
            float2 o1 = make_float2(acc[mt][nt][2] + bs.x, acc[mt][nt][3] + bs.y);
            *(float2*)&C[(size_t)row0 * N + col]       = o0;
            *(float2*)&C[(size_t)(row0 + 8) * N + col] = o1;
        }
    }
}

// ---------------------------------------------------------------------------
// Single-pass fp16 QKV GEMM: qkv = fp16(x) @ fp16(w) + bias, routed to
// head-contiguous fp16 Q(scaled)/K and fp16 pair-packed V.
// Stage: A 10240B + B 8704B = 18944B; 16 MMAs per k16-step.
// ---------------------------------------------------------------------------
#define QOFF_B    10240
#define QSTG_B    18944

__global__ __launch_bounds__(256, 2)
void hgemm_qkv_1p(const __half* __restrict__ Ah_g, const __half* __restrict__ Bh_g,
                  const float* __restrict__ bias,
                  __half* __restrict__ Q, __half* __restrict__ Kd,
                  __half* __restrict__ Vp,
                  int M, int N, int K)
{
    extern __shared__ char gsm[];
    const int tid  = threadIdx.x;
    const int warp = tid >> 5;
    const int lane = tid & 31;
    const int g  = lane >> 2;
    const int tg = lane & 3;

    const int bm = blockIdx.y * GBM;
    const int bn = blockIdx.x * GBN;
    const int warp_m = (warp >> 1) * 32;
    const int warp_n = (warp & 1) * 64;

    const int ar = tid >> 2, ac = (tid & 3) * 8;
    const int br = tid >> 4, bc = (tid & 15) * 8;
    const __half* ahg = Ah_g + (size_t)(bm + ar) * K + ac;
    const __half* bhg = Bh_g + (size_t)br * N + bn + bc;
    const size_t a64 = (size_t)64 * K;
    const size_t b16 = (size_t)16 * N;

    const uint32_t smb = (uint32_t)__cvta_generic_to_shared(gsm);
    const uint32_t dA  = (uint32_t)(ar * ASTR + ac) * 2;
    const uint32_t dA2 = (uint32_t)((ar + 64) * ASTR + ac) * 2;
    const uint32_t dB  = (uint32_t)(br * BSTR + bc) * 2;
    const uint32_t dB2 = (uint32_t)((br + 16) * BSTR + bc) * 2;

    float acc[2][8][4];
    #pragma unroll
    for (int mt = 0; mt < 2; mt++)
        #pragma unroll
        for (int nt = 0; nt < 8; nt++)
            #pragma unroll
            for (int i = 0; i < 4; i++) acc[mt][nt][i] = 0.f;

    const int NK = K / GBK;

    #define Q_ISSUE(s, kit) do {                                             \
        uint32_t so = smb + (uint32_t)(s) * QSTG_B;                          \
        size_t ka = (size_t)(kit) * GBK;                                     \
        size_t kb = (size_t)(kit) * GBK * (size_t)N;                         \
        cpasync16(so + dA,  ahg + ka);                                       \
        cpasync16(so + dA2, ahg + a64 + ka);                                 \
        cpasync16(so + QOFF_B + dB,  bhg + kb);                              \
        cpasync16(so + QOFF_B + dB2, bhg + b16 + kb);                        \
        asm volatile("cp.async.commit_group;");                              \
    } while (0)

    Q_ISSUE(0, 0);

    const int a_r = lane & 15;
    const int a_c = (lane >> 4) * 8;

    for (int it = 0; it < NK; it++) {
        if (it + 1 < NK) {
            Q_ISSUE((it + 1) & 1, it + 1);
            asm volatile("cp.async.wait_group 1;");
        } else {
            asm volatile("cp.async.wait_group 0;");
        }
        __syncthreads();

        const uint32_t sb = smb + (uint32_t)(it & 1) * QSTG_B;
        #pragma unroll
        for (int ks = 0; ks < 2; ks++) {
            const int kk = ks * 16;
            uint32_t ah[2][4];
            #pragma unroll
            for (int mt = 0; mt < 2; mt++) {
                uint32_t off = (uint32_t)((warp_m + mt * 16 + a_r) * ASTR + kk + a_c) * 2;
                ldsm4(ah[mt], sb + off);
            }
            #pragma unroll
            for (int np = 0; np < 4; np++) {
                uint32_t bh[4];
                uint32_t off = (uint32_t)((kk + a_r) * BSTR + warp_n + np * 16 + a_c) * 2;
                ldsm4t(bh, sb + QOFF_B + off);
                #pragma unroll
                for (int half = 0; half < 2; half++) {
                    const int nt = np * 2 + half;
                    #pragma unroll
                    for (int mt = 0; mt < 2; mt++) {
                        mma_f16(acc[mt][nt], ah[mt], bh[half * 2], bh[half * 2 + 1]);
                    }
                }
            }
        }
        __syncthreads();
    }
    #undef Q_ISSUE

    // epilogue: route to head-contiguous Q (scaled fp16), K (fp16), V (pair-packed)
    #pragma unroll
    for (int nt = 0; nt < 8; nt++) {
        const int col = bn + warp_n + nt * 8 + 2 * tg;      // col, col+1 (even)
        const float2 bs = *(const float2*)&bias[col];
        const int sec = col >> 10;            // 0=Q 1=K 2=V
        const int hh  = (col & 1023) >> 6;
        const int dd  = col & 63;
        #pragma unroll
        for (int mt = 0; mt < 2; mt++) {
            const int r0 = bm + warp_m + mt * 16 + g;
            #pragma unroll
            for (int rr = 0; rr < 2; rr++) {
                const int row = r0 + rr * 8;
                const int bb = row >> 11;
                const int tt = row & 2047;
                float v0 = acc[mt][nt][2 * rr]     + bs.x;
                float v1 = acc[mt][nt][2 * rr + 1] + bs.y;
                if (sec == 0) {
                    __half* p = Q + (((size_t)(bb * Hn + hh) * Tn + tt) << 6) + dd;
                    *(__half2*)p = __floats2half2_rn(v0 * SCALE, v1 * SCALE);
                } else if (sec == 1) {
                    __half* p = Kd + (((size_t)(bb * Hn + hh) * Tn + tt) << 6) + dd;
                    *(__half2*)p = __floats2half2_rn(v0, v1);
                } else {
                    __half* p = Vp + (((size_t)(bb * Hn + hh) * (Tn / 2)
                                       + (tt >> 1)) << 7) + (tt & 1);
                    p[dd * 2]       = __float2half_rn(v0);
                    p[(dd + 1) * 2] = __float2half_rn(v1);
                }
            }
        }
    }
}

// ===========================================================================
// Flash attention (R15 winner, unchanged): all-fp16 operands.
// Q: direct gmem A-frags. K, V: pure cp.async, triple buffer, 1 sync/tile.
// ===========================================================================
#define AT_BQ   128
#define AT_BKV  64
#define KHW     36
#define VSTR    72
#define KBUF_W  (AT_BKV * KHW)
#define VBUF_W  (32 * VSTR)
#define AT_SMEM ((3 * KBUF_W + 3 * VBUF_W) * 4)   // 55296 bytes

__global__ __launch_bounds__(256)
void attn_tc(const __half* __restrict__ gq, const __half* __restrict__ gk,
             const __half* __restrict__ gvp,
             __half* __restrict__ yhi, __half* __restrict__ ylo)
{
    extern __shared__ uint32_t apool[];

    const int b = blockIdx.z, h = blockIdx.y;
    const int qtile = gridDim.x - 1 - blockIdx.x;
    const int q0 = qtile * AT_BQ;
    const int tid  = threadIdx.x;
    const int warp = tid >> 5;
    const int lane = tid & 31;
    const int g  = lane >> 2;
    const int tg = lane & 3;

    const __half* kbp = gk  + ((size_t)(b * Hn + h) * Tn) * HDn;
    const __half* vbp = gvp + ((size_t)(b * Hn + h) * (Tn / 2)) * 2 * HDn;

    uint32_t Aq[4][4];
    {
        const uint32_t* qw = (const uint32_t*)(gq + ((size_t)(b * Hn + h) * Tn) * HDn);
        const int r0 = q0 + warp * 16 + g;
        #pragma unroll
        for (int kk = 0; kk < 4; kk++) {
            Aq[kk][0] = qw[(size_t)r0 * 32 + kk * 8 + tg];
            Aq[kk][1] = qw[(size_t)(r0 + 8) * 32 + kk * 8 + tg];
            Aq[kk][2] = qw[(size_t)r0 * 32 + kk * 8 + tg + 4];
            Aq[kk][3] = qw[(size_t)(r0 + 8) * 32 + kk * 8 + tg + 4];
        }
    }

    const uint32_t smb = (uint32_t)__cvta_generic_to_shared(apool);
    int krow[2], kcol[2]; uint32_t kdst[2];
    int vrow[2], vcol[2]; uint32_t vdst[2];
    #pragma unroll
    for (int i = 0; i < 2; i++) {
        int f = i * 256 + tid;
        krow[i] = f >> 3;
        kcol[i] = (f & 7) * 8;
        kdst[i] = (uint32_t)(krow[i] * KHW + (f & 7) * 4) * 4;
        vrow[i] = f >> 4;
        vcol[i] = (f & 15) * 8;
        vdst[i] = (uint32_t)(vrow[i] * VSTR + (f & 15) * 4) * 4;
    }

    const int NT = (q0 + AT_BQ) / AT_BKV;

    #define AT_ISSUE(tile, s) do {                                            \
        const uint32_t _ks = smb + (uint32_t)(s) * (KBUF_W * 4);              \
        const uint32_t _vs = smb + (uint32_t)(3 * KBUF_W + (s) * VBUF_W) * 4; \
        const int _kt = (tile) * AT_BKV;                                      \
        _Pragma("unroll")                                                     \
        for (int _i = 0; _i < 2; _i++) {                                      \
            cpasync16(_ks + kdst[_i],                                         \
                      kbp + (size_t)(_kt + krow[_i]) * HDn + kcol[_i]);       \
            cpasync16(_vs + vdst[_i],                                         \
                      vbp + (size_t)(_kt / 2 + vrow[_i]) * 2 * HDn + vcol[_i]);\
        }                                                                     \
        asm volatile("cp.async.commit_group;");                               \
    } while (0)

    AT_ISSUE(0, 0);
    if (NT > 1) AT_ISSUE(1, 1);

    float O[8][4];
    #pragma unroll
    for (int nt = 0; nt < 8; nt++)
        #pragma unroll
        for (int i = 0; i < 4; i++) O[nt][i] = 0.f;

    float m0 = -INFINITY, m1 = -INFINITY;
    float l0 = 0.f, l1 = 0.f;

    const int qi0 = q0 + warp * 16 + g;
    const int qi1 = qi0 + 8;
    const int w_qmax = q0 + warp * 16 + 15;
    const int w_qmin = q0 + warp * 16;

    for (int t = 0; t < NT; t++) {
        if (t + 1 < NT) asm volatile("cp.async.wait_group 1;");
        else            asm volatile("cp.async.wait_group 0;");
        __syncthreads();
        if (t + 2 < NT) AT_ISSUE(t + 2, (t + 2) % 3);

        const int kt = t * AT_BKV;
        const uint32_t* Kw = apool + (t % 3) * KBUF_W;
        const uint32_t* Vp = apool + 3 * KBUF_W + (t % 3) * VBUF_W;

        if (kt <= w_qmax) {
            float S[8][4];
            #pragma unroll
            for (int nt = 0; nt < 8; nt++) {
                S[nt][0] = S[nt][1] = S[nt][2] = S[nt][3] = 0.f;
            }
            #pragma unroll
            for (int kk = 0; kk < 4; kk++) {
                #pragma unroll
                for (int nt = 0; nt < 8; nt++) {
                    const int rw = (nt * 8 + g) * KHW + kk * 8 + tg;
                    mma_f16(S[nt], Aq[kk], Kw[rw], Kw[rw + 4]);
                }
            }

            const bool need_mask = (kt + AT_BKV - 1 > w_qmin);
            if (need_mask) {
                #pragma unroll
                for (int nt = 0; nt < 8; nt++) {
                    int j0 = kt + nt * 8 + 2 * tg;
                    int j1 = j0 + 1;
                    if (j0 > qi0) S[nt][0] = -INFINITY;
                    if (j1 > qi0) S[nt][1] = -INFINITY;
                    if (j0 > qi1) S[nt][2] = -INFINITY;
                    if (j1 > qi1) S[nt][3] = -INFINITY;
                }
            }

            float mc0 = -INFINITY, mc1 = -INFINITY;
            #pragma unroll
            for (int nt = 0; nt < 8; nt++) {
                mc0 = fmaxf(mc0, fmaxf(S[nt][0], S[nt][1]));
                mc1 = fmaxf(mc1, fmaxf(S[nt][2], S[nt][3]));
            }
            mc0 = fmaxf(mc0, __shfl_xor_sync(0xffffffffu, mc0, 1));
            mc0 = fmaxf(mc0, __shfl_xor_sync(0xffffffffu, mc0, 2));
            mc1 = fmaxf(mc1, __shfl_xor_sync(0xffffffffu, mc1, 1));
            mc1 = fmaxf(mc1, __shfl_xor_sync(0xffffffffu, mc1, 2));

            float mn0 = fmaxf(m0, mc0);
            float mn1 = fmaxf(m1, mc1);
            float corr0 = __expf(m0 - mn0);
            float corr1 = __expf(m1 - mn1);
            m0 = mn0; m1 = mn1;

            float ps0 = 0.f, ps1 = 0.f;
            #pragma unroll
            for (int nt = 0; nt < 8; nt++) {
                S[nt][0] = __expf(S[nt][0] - mn0);
                S[nt][1] = __expf(S[nt][1] - mn0);
                S[nt][2] = __expf(S[nt][2] - mn1);
                S[nt][3] = __expf(S[nt][3] - mn1);
                ps0 += S[nt][0] + S[nt][1];
                ps1 += S[nt][2] + S[nt][3];
            }
            ps0 += __shfl_xor_sync(0xffffffffu, ps0, 1);
            ps0 += __shfl_xor_sync(0xffffffffu, ps0, 2);
            ps1 += __shfl_xor_sync(0xffffffffu, ps1, 1);
            ps1 += __shfl_xor_sync(0xffffffffu, ps1, 2);
            l0 = l0 * corr0 + ps0;
            l1 = l1 * corr1 + ps1;

            #pragma unroll
            for (int nt = 0; nt < 8; nt++) {
                O[nt][0] *= corr0; O[nt][1] *= corr0;
                O[nt][2] *= corr1; O[nt][3] *= corr1;
            }

            #pragma unroll
            for (int s = 0; s < 4; s++) {
                uint32_t aph[4], apl[4];
                const float pv[8] = {
                    S[2*s  ][0], S[2*s  ][1], S[2*s  ][2], S[2*s  ][3],
                    S[2*s+1][0], S[2*s+1][1], S[2*s+1][2], S[2*s+1][3]
                };
                #pragma unroll
                for (int q = 0; q < 4; q++) {
                    __half2 hp = __floats2half2_rn(pv[2*q], pv[2*q+1]);
                    aph[q] = *(uint32_t*)&hp;
                    float2 hf = __half22float2(hp);
                    __half2 lp = __floats2half2_rn(pv[2*q] - hf.x, pv[2*q+1] - hf.y);
                    apl[q] = *(uint32_t*)&lp;
                }
                const int pr0 = (8 * s + tg) * VSTR;
                const int pr1 = (8 * s + tg + 4) * VSTR;
                #pragma unroll
                for (int dd = 0; dd < 8; dd++) {
                    const int dc = dd * 8 + g;
                    uint32_t b0 = Vp[pr0 + dc];
                    uint32_t b1 = Vp[pr1 + dc];
                    mma_f16(O[dd], aph, b0, b1);
                    mma_f16(O[dd], apl, b0, b1);
                }
            }
        }
    }
    #undef AT_ISSUE

    const float inv0 = 1.f / l0;
    const float inv1 = 1.f / l1;
    const size_t row0 = (size_t)(b * Tn + qi0) * Cn + h * HDn;
    const size_t row1 = (size_t)(b * Tn + qi1) * Cn + h * HDn;
    #pragma unroll
    for (int nt = 0; nt < 8; nt++) {
        int c = nt * 8 + 2 * tg;
        float v00 = O[nt][0] * inv0, v01 = O[nt][1] * inv0;
        float v10 = O[nt][2] * inv1, v11 = O[nt][3] * inv1;
        __half h00 = __float2half_rn(v00), h01 = __float2half_rn(v01);
        __half h10 = __float2half_rn(v10), h11 = __float2half_rn(v11);
        *(__half2*)&yhi[row0 + c] = __half2(h00, h01);
        *(__half2*)&yhi[row1 + c] = __half2(h10, h11);
        *(__half2*)&ylo[row0 + c] = __half2(
            __float2half_rn(v00 - __half2float(h00)),
            __float2half_rn(v01 - __half2float(h01)));
        *(__half2*)&ylo[row1 + c] = __half2(
            __float2half_rn(v10 - __half2float(h10)),
            __float2half_rn(v11 - __half2float(h11)));
    }
}

// ---------------------------------------------------------------------------
// Launch
// ---------------------------------------------------------------------------
extern "C" void kernel_launch(void* const* d_in, const int* in_sizes, int n_in,
                              void* d_out, int out_size)
{
    const float* x      = (const float*)d_in[0];
    const float* w_attn = (const float*)d_in[1];
    const float* b_attn = (const float*)d_in[2];
    const float* w_proj = (const float*)d_in[3];
    const float* b_proj = (const float*)d_in[4];
    float* out = (float*)d_out;

    __half *gq, *gk, *gvp, *xh, *wah, *wph, *yhi, *ylo;
    cudaGetSymbolAddress((void**)&gq,  g_q);
    cudaGetSymbolAddress((void**)&gk,  g_k);
    cudaGetSymbolAddress((void**)&gvp, g_vp);
    cudaGetSymbolAddress((void**)&xh,  g_xh);
    cudaGetSymbolAddress((void**)&wah, g_wah);
    cudaGetSymbolAddress((void**)&wph, g_wph);
    cudaGetSymbolAddress((void**)&yhi, g_yhi);
    cudaGetSymbolAddress((void**)&ylo, g_ylo);

    cudaFuncSetAttribute(hgemm_2p,     cudaFuncAttributeMaxDynamicSharedMemorySize, GEMM_SMEM);
    cudaFuncSetAttribute(hgemm_qkv_1p, cudaFuncAttributeMaxDynamicSharedMemorySize, 2 * QSTG_B);
    cudaFuncSetAttribute(attn_tc,      cudaFuncAttributeMaxDynamicSharedMemorySize, AT_SMEM);

    // 0) convert x and weights to fp16
    {
        int n4;
        n4 = (Mrows * Cn) / 4;
        conv_h<<<(n4 + 255) / 256, 256>>>(x, xh, n4);
        n4 = (Cn * QKV_N) / 4;
        conv_h<<<(n4 + 255) / 256, 256>>>(w_attn, wah, n4);
        n4 = (Cn * Cn) / 4;
        conv_h<<<(n4 + 255) / 256, 256>>>(w_proj, wph, n4);
    }
    // 1) QKV projection (single-pass fp16) -> head-contiguous Q/K/V
    {
        dim3 grid(QKV_N / GBN, Mrows / GBM);
        hgemm_qkv_1p<<<grid, 256, 2 * QSTG_B>>>(xh, wah, b_attn,
                                                gq, gk, gvp, Mrows, QKV_N, Cn);
    }
    // 2) Causal attention (all-fp16, pure cp.async staging)
    {
        dim3 grid(Tn / AT_BQ, Hn, Bn);
        attn_tc<<<grid, 256, AT_SMEM>>>(gq, gk, gvp, yhi, ylo);
    }
    // 3) Output projection (2-pass fp16, accuracy-critical path)
    {
        dim3 grid(Cn / GBN, Mrows / GBM);
        hgemm_2p<<<grid, 256, GEMM_SMEM>>>(yhi, ylo, wph, b_proj,
                                           out, Mrows, Cn, Cn);
    }
}